// round 1
// baseline (speedup 1.0000x reference)
#include <cuda_runtime.h>
#include <cuda_bf16.h>

#define Bn  8
#define Tn  2048
#define Dn  1024
#define HSn 128

// Scratch for projected K/Q/V: [B*T, HS] fp32 each (8 MB each, 24 MB total).
__device__ float g_k[Bn * Tn * HSn];
__device__ float g_q[Bn * Tn * HSn];
__device__ float g_v[Bn * Tn * HSn];

// ---------------------------------------------------------------------------
// Projection GEMM: out[m][n] = sum_d x[m][d] * W[n][d]
//   M = B*T = 16384, N = HS = 128, K = D = 1024
// blockIdx.z in {0,1,2} selects (Wk->g_k, Wq->g_q, Wv->g_v).
// Tile: BM=64, BN=64, BK=16; 256 threads; 4x4 micro-tile per thread.
// ---------------------------------------------------------------------------
__global__ __launch_bounds__(256) void proj_kernel(
    const float* __restrict__ x,
    const float* __restrict__ Wk,
    const float* __restrict__ Wq,
    const float* __restrict__ Wv)
{
    const float* W;
    float* outp;
    if (blockIdx.z == 0)      { W = Wk; outp = g_k; }
    else if (blockIdx.z == 1) { W = Wq; outp = g_q; }
    else                      { W = Wv; outp = g_v; }

    __shared__ float Xs[64][17];   // padded stride 17 -> ~conflict-free
    __shared__ float Ws[64][17];

    const int m0 = blockIdx.x * 64;
    const int n0 = blockIdx.y * 64;
    const int t  = threadIdx.x;
    const int tx = t & 15;         // 0..15 -> output cols tx*4..+3
    const int ty = t >> 4;         // 0..15 -> output rows ty*4..+3

    // Loader mapping: each thread loads one float4 per matrix per k-tile.
    const int lrow = t >> 2;          // 0..63
    const int lcol = (t & 3) * 4;     // 0,4,8,12

    float acc[4][4] = {};

    for (int k0 = 0; k0 < Dn; k0 += 16) {
        float4 xa = *(const float4*)&x[(m0 + lrow) * Dn + k0 + lcol];
        float4 wa = *(const float4*)&W[(n0 + lrow) * Dn + k0 + lcol];
        Xs[lrow][lcol + 0] = xa.x; Xs[lrow][lcol + 1] = xa.y;
        Xs[lrow][lcol + 2] = xa.z; Xs[lrow][lcol + 3] = xa.w;
        Ws[lrow][lcol + 0] = wa.x; Ws[lrow][lcol + 1] = wa.y;
        Ws[lrow][lcol + 2] = wa.z; Ws[lrow][lcol + 3] = wa.w;
        __syncthreads();

        #pragma unroll
        for (int k = 0; k < 16; k++) {
            float a[4], b[4];
            #pragma unroll
            for (int i = 0; i < 4; i++) a[i] = Xs[ty * 4 + i][k];
            #pragma unroll
            for (int j = 0; j < 4; j++) b[j] = Ws[tx * 4 + j][k];
            #pragma unroll
            for (int i = 0; i < 4; i++)
                #pragma unroll
                for (int j = 0; j < 4; j++)
                    acc[i][j] += a[i] * b[j];
        }
        __syncthreads();
    }

    #pragma unroll
    for (int i = 0; i < 4; i++)
        #pragma unroll
        for (int j = 0; j < 4; j++)
            outp[(m0 + ty * 4 + i) * HSn + n0 + tx * 4 + j] = acc[i][j];
}

// ---------------------------------------------------------------------------
// Flash-attention (fp32, online softmax).
// Grid: (T/64, B); block 256 threads.
// Per block: 64 query rows. Iterate causal key tiles of 64 rows.
// Thread (ty,tx): owns S[4x4] sub-tile (rows ty*4.., key-cols tx*4..) and
// O accumulator rows ty*4.. x dims tx*8..+7.
// qb is reversed so the heaviest (longest-loop) blocks launch first.
// ---------------------------------------------------------------------------
#define QK_STRIDE 129
#define V_STRIDE  128
#define P_STRIDE  65

__global__ __launch_bounds__(256) void attn_kernel(float* __restrict__ out)
{
    extern __shared__ float sm[];
    float* Qs = sm;                                 // [64][129]
    float* Ks = Qs + 64 * QK_STRIDE;                // [64][129]
    float* Vs = Ks + 64 * QK_STRIDE;                // [64][128]
    float* Ps = Vs + 64 * V_STRIDE;                 // [64][65]

    const int qb = (gridDim.x - 1) - blockIdx.x;    // heavy blocks first
    const int b  = blockIdx.y;
    const int t  = threadIdx.x;
    const int tx = t & 15;
    const int ty = t >> 4;

    const float scale = 0.08838834764831845f;       // 1/sqrt(128)

    // ---- load Q tile into smem (once) ----
    const float* qg = g_q + (size_t)(b * Tn + qb * 64) * HSn;
    #pragma unroll
    for (int it = 0; it < 8; it++) {
        int idx = it * 256 + t;                     // 0..2047 float4 units
        int r = idx >> 5;
        int cg = (idx & 31) * 4;
        float4 v = *(const float4*)&qg[r * HSn + cg];
        Qs[r * QK_STRIDE + cg + 0] = v.x;
        Qs[r * QK_STRIDE + cg + 1] = v.y;
        Qs[r * QK_STRIDE + cg + 2] = v.z;
        Qs[r * QK_STRIDE + cg + 3] = v.w;
    }

    float m_i[4], l_i[4];
    float o[4][8] = {};
    #pragma unroll
    for (int i = 0; i < 4; i++) { m_i[i] = -1e30f; l_i[i] = 0.0f; }

    for (int kb = 0; kb <= qb; kb++) {
        __syncthreads();   // previous PV-update (reads Ks/Vs/Ps) done

        // ---- load K, V tiles ----
        const float* kg = g_k + (size_t)(b * Tn + kb * 64) * HSn;
        const float* vg = g_v + (size_t)(b * Tn + kb * 64) * HSn;
        #pragma unroll
        for (int it = 0; it < 8; it++) {
            int idx = it * 256 + t;
            int r = idx >> 5;
            int cg = (idx & 31) * 4;
            float4 kv = *(const float4*)&kg[r * HSn + cg];
            Ks[r * QK_STRIDE + cg + 0] = kv.x;
            Ks[r * QK_STRIDE + cg + 1] = kv.y;
            Ks[r * QK_STRIDE + cg + 2] = kv.z;
            Ks[r * QK_STRIDE + cg + 3] = kv.w;
            float4 vv = *(const float4*)&vg[r * HSn + cg];
            *(float4*)&Vs[r * V_STRIDE + cg] = vv;
        }
        __syncthreads();

        // ---- S = Q K^T (4x4 per thread) ----
        float s[4][4] = {};
        #pragma unroll 8
        for (int d = 0; d < HSn; d++) {
            float a[4], bb[4];
            #pragma unroll
            for (int i = 0; i < 4; i++) a[i]  = Qs[(ty * 4 + i) * QK_STRIDE + d];
            #pragma unroll
            for (int j = 0; j < 4; j++) bb[j] = Ks[(tx * 4 + j) * QK_STRIDE + d];
            #pragma unroll
            for (int i = 0; i < 4; i++)
                #pragma unroll
                for (int j = 0; j < 4; j++)
                    s[i][j] += a[i] * bb[j];
        }

        // ---- scale + causal mask (only diagonal tile needs masking) ----
        const bool diag = (kb == qb);
        #pragma unroll
        for (int i = 0; i < 4; i++)
            #pragma unroll
            for (int j = 0; j < 4; j++) {
                float v = s[i][j] * scale;
                if (diag && (tx * 4 + j) > (ty * 4 + i)) v = -1e30f;
                s[i][j] = v;
            }

        // ---- online softmax: per-row max/sum across the 16 tx threads ----
        #pragma unroll
        for (int i = 0; i < 4; i++) {
            float mx = fmaxf(fmaxf(s[i][0], s[i][1]), fmaxf(s[i][2], s[i][3]));
            #pragma unroll
            for (int off = 8; off >= 1; off >>= 1)
                mx = fmaxf(mx, __shfl_xor_sync(0xffffffffu, mx, off, 16));

            float mnew = fmaxf(m_i[i], mx);
            float corr = __expf(m_i[i] - mnew);
            m_i[i] = mnew;

            float rs = 0.0f;
            #pragma unroll
            for (int j = 0; j < 4; j++) {
                s[i][j] = __expf(s[i][j] - mnew);
                rs += s[i][j];
            }
            #pragma unroll
            for (int off = 8; off >= 1; off >>= 1)
                rs += __shfl_xor_sync(0xffffffffu, rs, off, 16);

            l_i[i] = l_i[i] * corr + rs;
            #pragma unroll
            for (int c = 0; c < 8; c++) o[i][c] *= corr;

            #pragma unroll
            for (int j = 0; j < 4; j++)
                Ps[(ty * 4 + i) * P_STRIDE + tx * 4 + j] = s[i][j];
        }
        __syncthreads();   // Ps visible to all

        // ---- O += P @ V ----
        #pragma unroll 4
        for (int j = 0; j < 64; j++) {
            float p0 = Ps[(ty * 4 + 0) * P_STRIDE + j];
            float p1 = Ps[(ty * 4 + 1) * P_STRIDE + j];
            float p2 = Ps[(ty * 4 + 2) * P_STRIDE + j];
            float p3 = Ps[(ty * 4 + 3) * P_STRIDE + j];
            float4 v0 = *(const float4*)&Vs[j * V_STRIDE + tx * 8];
            float4 v1 = *(const float4*)&Vs[j * V_STRIDE + tx * 8 + 4];
            o[0][0] += p0 * v0.x; o[0][1] += p0 * v0.y; o[0][2] += p0 * v0.z; o[0][3] += p0 * v0.w;
            o[0][4] += p0 * v1.x; o[0][5] += p0 * v1.y; o[0][6] += p0 * v1.z; o[0][7] += p0 * v1.w;
            o[1][0] += p1 * v0.x; o[1][1] += p1 * v0.y; o[1][2] += p1 * v0.z; o[1][3] += p1 * v0.w;
            o[1][4] += p1 * v1.x; o[1][5] += p1 * v1.y; o[1][6] += p1 * v1.z; o[1][7] += p1 * v1.w;
            o[2][0] += p2 * v0.x; o[2][1] += p2 * v0.y; o[2][2] += p2 * v0.z; o[2][3] += p2 * v0.w;
            o[2][4] += p2 * v1.x; o[2][5] += p2 * v1.y; o[2][6] += p2 * v1.z; o[2][7] += p2 * v1.w;
            o[3][0] += p3 * v0.x; o[3][1] += p3 * v0.y; o[3][2] += p3 * v0.z; o[3][3] += p3 * v0.w;
            o[3][4] += p3 * v1.x; o[3][5] += p3 * v1.y; o[3][6] += p3 * v1.z; o[3][7] += p3 * v1.w;
        }
    }

    // ---- epilogue: O / l -> out ----
    float* og = out + (size_t)(b * Tn + qb * 64) * HSn;
    #pragma unroll
    for (int i = 0; i < 4; i++) {
        float inv = 1.0f / l_i[i];
        float4 r0 = make_float4(o[i][0] * inv, o[i][1] * inv, o[i][2] * inv, o[i][3] * inv);
        float4 r1 = make_float4(o[i][4] * inv, o[i][5] * inv, o[i][6] * inv, o[i][7] * inv);
        *(float4*)&og[(ty * 4 + i) * HSn + tx * 8]     = r0;
        *(float4*)&og[(ty * 4 + i) * HSn + tx * 8 + 4] = r1;
    }
}

// ---------------------------------------------------------------------------
extern "C" void kernel_launch(void* const* d_in, const int* in_sizes, int n_in,
                              void* d_out, int out_size)
{
    const float* x  = (const float*)d_in[0];
    const float* Wk = (const float*)d_in[1];
    const float* Wq = (const float*)d_in[2];
    const float* Wv = (const float*)d_in[3];
    float* out = (float*)d_out;

    // Projections: K/Q/V = x @ W^T
    dim3 pg(Bn * Tn / 64, HSn / 64, 3);
    proj_kernel<<<pg, 256>>>(x, Wk, Wq, Wv);

    // Flash attention
    const int smem_bytes = (64 * QK_STRIDE * 2 + 64 * V_STRIDE + 64 * P_STRIDE) * (int)sizeof(float);
    cudaFuncSetAttribute(attn_kernel, cudaFuncAttributeMaxDynamicSharedMemorySize, smem_bytes);
    dim3 ag(Tn / 64, Bn);
    attn_kernel<<<ag, 256, smem_bytes>>>(out);
}

// round 2
// speedup vs baseline: 2.1592x; 2.1592x over previous
#include <cuda_runtime.h>

#define Bn  8
#define Tn  2048
#define Dn  1024
#define HSn 128

// Scratch for projected K/Q/V: [B*T, HS] fp32 each.
__device__ float g_k[Bn * Tn * HSn];
__device__ float g_q[Bn * Tn * HSn];
__device__ float g_v[Bn * Tn * HSn];

// fp32 -> tf32 (round-to-nearest) bit pattern
__device__ __forceinline__ unsigned f2tf(float f) {
    unsigned u;
    asm("cvt.rna.tf32.f32 %0, %1;" : "=r"(u) : "f"(f));
    return u;
}

// mma.sync m16n8k8 tf32: C += A(16x8,row) * B(8x8,col)
__device__ __forceinline__ void mma8(float* c,
                                     unsigned a0, unsigned a1, unsigned a2, unsigned a3,
                                     unsigned b0, unsigned b1) {
    asm volatile(
        "mma.sync.aligned.m16n8k8.row.col.f32.tf32.tf32.f32 "
        "{%0,%1,%2,%3},{%4,%5,%6,%7},{%8,%9},{%0,%1,%2,%3};"
        : "+f"(c[0]), "+f"(c[1]), "+f"(c[2]), "+f"(c[3])
        : "r"(a0), "r"(a1), "r"(a2), "r"(a3), "r"(b0), "r"(b1));
}

// permute a column index within its 8-group so (k, k+4) become adjacent
__device__ __forceinline__ int pcol(int c) {
    return (c & ~7) | ((c & 3) << 1) | ((c & 4) >> 2);
}

// ---------------------------------------------------------------------------
// Projection GEMM (tf32 MMA): out[m][n] = sum_d x[m][d] * W[n][d]
// M=16384, N=128, K=1024.  BM=128, BN=128, BK=16.  256 threads, 8 warps (4m x 2n).
// ---------------------------------------------------------------------------
__global__ __launch_bounds__(256, 2) void proj_kernel(
    const float* __restrict__ x,
    const float* __restrict__ Wk,
    const float* __restrict__ Wq,
    const float* __restrict__ Wv)
{
    __shared__ unsigned Xs[128][20];   // 16 k-cols pair-permuted + pad
    __shared__ unsigned Ws[128][20];

    const float* W;
    float* outp;
    if (blockIdx.z == 0)      { W = Wk; outp = g_k; }
    else if (blockIdx.z == 1) { W = Wq; outp = g_q; }
    else                      { W = Wv; outp = g_v; }

    const int m0   = blockIdx.x * 128;
    const int t    = threadIdx.x;
    const int lane = t & 31;
    const int w    = t >> 5;
    const int wm   = w & 3;          // 0..3 -> rows 32*wm
    const int wn   = w >> 2;         // 0..1 -> cols 64*wn
    const int lg   = lane >> 2;      // groupID 0..7
    const int lt   = lane & 3;       // threadID-in-group 0..3

    const int lrow  = t >> 1;        // 0..127
    const int lhalf = (t & 1) * 8;   // col base 0 or 8

    float acc[2][8][4];
    #pragma unroll
    for (int mf = 0; mf < 2; mf++)
        #pragma unroll
        for (int j = 0; j < 8; j++)
            #pragma unroll
            for (int r = 0; r < 4; r++) acc[mf][j][r] = 0.0f;

    for (int k0 = 0; k0 < Dn; k0 += 16) {
        float4 xa = *(const float4*)&x[(size_t)(m0 + lrow) * Dn + k0 + lhalf];
        float4 xb = *(const float4*)&x[(size_t)(m0 + lrow) * Dn + k0 + lhalf + 4];
        float4 wa = *(const float4*)&W[(size_t)lrow * Dn + k0 + lhalf];
        float4 wb = *(const float4*)&W[(size_t)lrow * Dn + k0 + lhalf + 4];
        __syncthreads();
        // first float4: kk=0..3 -> positions lhalf + 2i ; second: kk=4..7 -> lhalf+1+2i
        Xs[lrow][lhalf + 0] = f2tf(xa.x); Xs[lrow][lhalf + 2] = f2tf(xa.y);
        Xs[lrow][lhalf + 4] = f2tf(xa.z); Xs[lrow][lhalf + 6] = f2tf(xa.w);
        Xs[lrow][lhalf + 1] = f2tf(xb.x); Xs[lrow][lhalf + 3] = f2tf(xb.y);
        Xs[lrow][lhalf + 5] = f2tf(xb.z); Xs[lrow][lhalf + 7] = f2tf(xb.w);
        Ws[lrow][lhalf + 0] = f2tf(wa.x); Ws[lrow][lhalf + 2] = f2tf(wa.y);
        Ws[lrow][lhalf + 4] = f2tf(wa.z); Ws[lrow][lhalf + 6] = f2tf(wa.w);
        Ws[lrow][lhalf + 1] = f2tf(wb.x); Ws[lrow][lhalf + 3] = f2tf(wb.y);
        Ws[lrow][lhalf + 5] = f2tf(wb.z); Ws[lrow][lhalf + 7] = f2tf(wb.w);
        __syncthreads();

        #pragma unroll
        for (int ks = 0; ks < 2; ks++) {
            unsigned a[2][4];
            #pragma unroll
            for (int mf = 0; mf < 2; mf++) {
                int row = wm * 32 + mf * 16 + lg;
                uint2 a02 = *(const uint2*)&Xs[row][ks * 8 + 2 * lt];
                uint2 a13 = *(const uint2*)&Xs[row + 8][ks * 8 + 2 * lt];
                a[mf][0] = a02.x; a[mf][1] = a13.x; a[mf][2] = a02.y; a[mf][3] = a13.y;
            }
            #pragma unroll
            for (int j = 0; j < 8; j++) {
                uint2 b = *(const uint2*)&Ws[wn * 64 + j * 8 + lg][ks * 8 + 2 * lt];
                mma8(acc[0][j], a[0][0], a[0][1], a[0][2], a[0][3], b.x, b.y);
                mma8(acc[1][j], a[1][0], a[1][1], a[1][2], a[1][3], b.x, b.y);
            }
        }
    }

    #pragma unroll
    for (int mf = 0; mf < 2; mf++)
        #pragma unroll
        for (int j = 0; j < 8; j++) {
            int row = m0 + wm * 32 + mf * 16 + lg;
            int col = wn * 64 + j * 8 + 2 * lt;
            *(float2*)&outp[(size_t)row * HSn + col]       = make_float2(acc[mf][j][0], acc[mf][j][1]);
            *(float2*)&outp[(size_t)(row + 8) * HSn + col] = make_float2(acc[mf][j][2], acc[mf][j][3]);
        }
}

// ---------------------------------------------------------------------------
// Flash attention with tf32 MMA.
// BM=64 queries, BN=64 keys, 256 threads (8 warps).
// QK^T: warp grid 4(m) x 2(n). PV as O^T = V^T * P^T: warp grid 4(dims) x 2(queries).
// CTA pairs query blocks (pair, 31-pair) -> perfectly balanced 33 key-tiles each.
// ---------------------------------------------------------------------------
#define QSTR 132
#define PSTR 68
#define ATTN_SMEM_UNITS (64 * QSTR * 3 + 64 * PSTR + 128 + 128 + 64 * 4)

__global__ __launch_bounds__(256, 1) void attn_kernel(float* __restrict__ out)
{
    extern __shared__ unsigned sm[];
    unsigned* Qs = sm;                 // [64][QSTR] tf32, pair-permuted cols
    unsigned* Ks = Qs + 64 * QSTR;     // [64][QSTR] tf32, pair-permuted cols
    unsigned* Vs = Ks + 64 * QSTR;     // [64][QSTR] tf32, natural cols
    unsigned* Ps = Vs + 64 * QSTR;     // [64][PSTR] tf32, pair-permuted cols
    float* pmax = (float*)(Ps + 64 * PSTR);  // [64][2]
    float* psum = pmax + 128;                // [64][2]
    float* mst  = psum + 128;                // [64]
    float* lst  = mst + 64;                  // [64]
    float* cors = lst + 64;                  // [64]
    float* linv = cors + 64;                 // [64]

    const int b    = blockIdx.y;
    const int pair = blockIdx.x;
    const int t    = threadIdx.x;
    const int lane = t & 31;
    const int w    = t >> 5;
    const int wm   = w & 3;       // QK rows 16*wm    / PV dims 32*wm
    const int wn   = w >> 2;      // QK cols 32*wn    / PV queries 32*wn
    const int lg   = lane >> 2;
    const int lt   = lane & 3;

    const float scale = 0.08838834764831845f;  // 1/sqrt(128)

    const int lrow = t >> 2;          // 0..63  (tile loader)
    const int lq4  = (t & 3) * 32;    // col quarter base

    for (int qidx = 0; qidx < 2; qidx++) {
        const int qb = qidx ? (31 - pair) : pair;

        // ---- load Q tile (scaled, tf32, pair-permuted) ----
        const float* qg = g_q + (size_t)(b * Tn + qb * 64) * HSn;
        #pragma unroll
        for (int i = 0; i < 8; i++) {
            int c = lq4 + i * 4;
            float4 v = *(const float4*)&qg[lrow * HSn + c];
            int g = c & ~7, off = (c & 4) ? 1 : 0;
            Qs[lrow * QSTR + g + off + 0] = f2tf(v.x * scale);
            Qs[lrow * QSTR + g + off + 2] = f2tf(v.y * scale);
            Qs[lrow * QSTR + g + off + 4] = f2tf(v.z * scale);
            Qs[lrow * QSTR + g + off + 6] = f2tf(v.w * scale);
        }
        if (t < 64) { mst[t] = -1e30f; lst[t] = 0.0f; }

        float o[2][4][4];
        #pragma unroll
        for (int mf = 0; mf < 2; mf++)
            #pragma unroll
            for (int j = 0; j < 4; j++)
                #pragma unroll
                for (int r = 0; r < 4; r++) o[mf][j][r] = 0.0f;

        for (int kb = 0; kb <= qb; kb++) {
            __syncthreads();
            // ---- load K (permuted), V (natural) ----
            const float* kg = g_k + (size_t)(b * Tn + kb * 64) * HSn;
            const float* vg = g_v + (size_t)(b * Tn + kb * 64) * HSn;
            #pragma unroll
            for (int i = 0; i < 8; i++) {
                int c = lq4 + i * 4;
                float4 kv = *(const float4*)&kg[lrow * HSn + c];
                int g = c & ~7, off = (c & 4) ? 1 : 0;
                Ks[lrow * QSTR + g + off + 0] = f2tf(kv.x);
                Ks[lrow * QSTR + g + off + 2] = f2tf(kv.y);
                Ks[lrow * QSTR + g + off + 4] = f2tf(kv.z);
                Ks[lrow * QSTR + g + off + 6] = f2tf(kv.w);
                float4 vv = *(const float4*)&vg[lrow * HSn + c];
                uint4 u;
                u.x = f2tf(vv.x); u.y = f2tf(vv.y); u.z = f2tf(vv.z); u.w = f2tf(vv.w);
                *(uint4*)&Vs[lrow * QSTR + c] = u;
            }
            __syncthreads();

            // ---- S = Q K^T : per warp 16 rows x 32 cols ----
            float s[4][4];
            #pragma unroll
            for (int j = 0; j < 4; j++)
                #pragma unroll
                for (int r = 0; r < 4; r++) s[j][r] = 0.0f;

            const int qrow = wm * 16 + lg;
            #pragma unroll
            for (int ks = 0; ks < 16; ks++) {
                uint2 a02 = *(const uint2*)&Qs[qrow * QSTR + ks * 8 + 2 * lt];
                uint2 a13 = *(const uint2*)&Qs[(qrow + 8) * QSTR + ks * 8 + 2 * lt];
                #pragma unroll
                for (int j = 0; j < 4; j++) {
                    uint2 bf = *(const uint2*)&Ks[(wn * 32 + j * 8 + lg) * QSTR + ks * 8 + 2 * lt];
                    mma8(s[j], a02.x, a13.x, a02.y, a13.y, bf.x, bf.y);
                }
            }

            // ---- causal mask on diagonal tile ----
            if (kb == qb) {
                const int rl0 = wm * 16 + lg, rl1 = rl0 + 8;
                #pragma unroll
                for (int j = 0; j < 4; j++) {
                    int cl = wn * 32 + j * 8 + 2 * lt;
                    if (cl     > rl0) s[j][0] = -1e30f;
                    if (cl + 1 > rl0) s[j][1] = -1e30f;
                    if (cl     > rl1) s[j][2] = -1e30f;
                    if (cl + 1 > rl1) s[j][3] = -1e30f;
                }
            }

            // ---- partial row max (32 cols per warp-strip) ----
            const int r0 = wm * 16 + lg, r1 = r0 + 8;
            float mx0 = -1e30f, mx1 = -1e30f;
            #pragma unroll
            for (int j = 0; j < 4; j++) {
                mx0 = fmaxf(mx0, fmaxf(s[j][0], s[j][1]));
                mx1 = fmaxf(mx1, fmaxf(s[j][2], s[j][3]));
            }
            mx0 = fmaxf(mx0, __shfl_xor_sync(0xffffffffu, mx0, 1));
            mx0 = fmaxf(mx0, __shfl_xor_sync(0xffffffffu, mx0, 2));
            mx1 = fmaxf(mx1, __shfl_xor_sync(0xffffffffu, mx1, 1));
            mx1 = fmaxf(mx1, __shfl_xor_sync(0xffffffffu, mx1, 2));
            if (lt == 0) { pmax[r0 * 2 + wn] = mx0; pmax[r1 * 2 + wn] = mx1; }
            __syncthreads();

            // ---- exp + partial sums + store P (tf32, pair-permuted) ----
            const float mn0 = fmaxf(mst[r0], fmaxf(pmax[r0 * 2], pmax[r0 * 2 + 1]));
            const float mn1 = fmaxf(mst[r1], fmaxf(pmax[r1 * 2], pmax[r1 * 2 + 1]));
            float sum0 = 0.0f, sum1 = 0.0f;
            #pragma unroll
            for (int j = 0; j < 4; j++) {
                s[j][0] = __expf(s[j][0] - mn0); sum0 += s[j][0];
                s[j][1] = __expf(s[j][1] - mn0); sum0 += s[j][1];
                s[j][2] = __expf(s[j][2] - mn1); sum1 += s[j][2];
                s[j][3] = __expf(s[j][3] - mn1); sum1 += s[j][3];
            }
            sum0 += __shfl_xor_sync(0xffffffffu, sum0, 1);
            sum0 += __shfl_xor_sync(0xffffffffu, sum0, 2);
            sum1 += __shfl_xor_sync(0xffffffffu, sum1, 1);
            sum1 += __shfl_xor_sync(0xffffffffu, sum1, 2);
            if (lt == 0) { psum[r0 * 2 + wn] = sum0; psum[r1 * 2 + wn] = sum1; }

            #pragma unroll
            for (int j = 0; j < 4; j++) {
                int cb = wn * 32 + j * 8;
                int p0 = cb + pcol(2 * lt);
                int p1 = cb + pcol(2 * lt + 1);
                Ps[r0 * PSTR + p0] = f2tf(s[j][0]);
                Ps[r0 * PSTR + p1] = f2tf(s[j][1]);
                Ps[r1 * PSTR + p0] = f2tf(s[j][2]);
                Ps[r1 * PSTR + p1] = f2tf(s[j][3]);
            }
            __syncthreads();

            // ---- owner threads update running (m, l) and publish corr ----
            if (t < 64) {
                float mo = mst[t];
                float mn = fmaxf(mo, fmaxf(pmax[t * 2], pmax[t * 2 + 1]));
                float cr = __expf(mo - mn);
                lst[t] = lst[t] * cr + psum[t * 2] + psum[t * 2 + 1];
                mst[t] = mn;
                cors[t] = cr;
            }
            __syncthreads();

            // ---- O^T accumulate: scale by corr, then O^T += V^T P^T ----
            #pragma unroll
            for (int j = 0; j < 4; j++) {
                int q0 = wn * 32 + j * 8 + 2 * lt;
                float c0 = cors[q0], c1 = cors[q0 + 1];
                #pragma unroll
                for (int mf = 0; mf < 2; mf++) {
                    o[mf][j][0] *= c0; o[mf][j][1] *= c1;
                    o[mf][j][2] *= c0; o[mf][j][3] *= c1;
                }
            }
            #pragma unroll
            for (int ks = 0; ks < 8; ks++) {
                unsigned a[2][4];
                #pragma unroll
                for (int mf = 0; mf < 2; mf++) {
                    int dim = wm * 32 + mf * 16 + lg;
                    a[mf][0] = Vs[(ks * 8 + lt)     * QSTR + dim];
                    a[mf][1] = Vs[(ks * 8 + lt)     * QSTR + dim + 8];
                    a[mf][2] = Vs[(ks * 8 + lt + 4) * QSTR + dim];
                    a[mf][3] = Vs[(ks * 8 + lt + 4) * QSTR + dim + 8];
                }
                #pragma unroll
                for (int j = 0; j < 4; j++) {
                    uint2 bb = *(const uint2*)&Ps[(wn * 32 + j * 8 + lg) * PSTR + ks * 8 + 2 * lt];
                    mma8(o[0][j], a[0][0], a[0][1], a[0][2], a[0][3], bb.x, bb.y);
                    mma8(o[1][j], a[1][0], a[1][1], a[1][2], a[1][3], bb.x, bb.y);
                }
            }
        } // kb

        __syncthreads();
        if (t < 64) linv[t] = 1.0f / lst[t];
        __syncthreads();

        // ---- epilogue: transpose-write O (regs hold O^T) ----
        float* og = out + (size_t)(b * Tn + qb * 64) * HSn;
        #pragma unroll
        for (int mf = 0; mf < 2; mf++)
            #pragma unroll
            for (int j = 0; j < 4; j++) {
                int dim = wm * 32 + mf * 16 + lg;
                int q0  = wn * 32 + j * 8 + 2 * lt;
                float li0 = linv[q0], li1 = linv[q0 + 1];
                og[(size_t)q0 * HSn + dim]           = o[mf][j][0] * li0;
                og[(size_t)(q0 + 1) * HSn + dim]     = o[mf][j][1] * li1;
                og[(size_t)q0 * HSn + dim + 8]       = o[mf][j][2] * li0;
                og[(size_t)(q0 + 1) * HSn + dim + 8] = o[mf][j][3] * li1;
            }
        __syncthreads();  // protect smem state before next qidx overwrites
    } // qidx
}

// ---------------------------------------------------------------------------
extern "C" void kernel_launch(void* const* d_in, const int* in_sizes, int n_in,
                              void* d_out, int out_size)
{
    const float* x  = (const float*)d_in[0];
    const float* Wk = (const float*)d_in[1];
    const float* Wq = (const float*)d_in[2];
    const float* Wv = (const float*)d_in[3];
    float* out = (float*)d_out;

    dim3 pg(Bn * Tn / 128, 1, 3);
    proj_kernel<<<pg, 256>>>(x, Wk, Wq, Wv);

    const int smem_bytes = ATTN_SMEM_UNITS * (int)sizeof(unsigned);
    cudaFuncSetAttribute(attn_kernel, cudaFuncAttributeMaxDynamicSharedMemorySize, smem_bytes);
    dim3 ag(Tn / 64 / 2, Bn);   // 16 pairs x 8 batches
    attn_kernel<<<ag, 256, smem_bytes>>>(out);
}

// round 3
// speedup vs baseline: 3.1456x; 1.4568x over previous
#include <cuda_runtime.h>

#define Bn  8
#define Tn  2048
#define Dn  1024
#define HSn 128

// Scratch: projected K/Q/V, split-K partial outputs, partial m/l.
__device__ float g_k[Bn * Tn * HSn];
__device__ float g_q[Bn * Tn * HSn];
__device__ float g_v[Bn * Tn * HSn];
__device__ float g_po[2 * Bn * Tn * HSn];
__device__ float g_pm[2 * Bn * Tn];
__device__ float g_pl[2 * Bn * Tn];

__device__ __forceinline__ unsigned f2tf(float f) {
    unsigned u;
    asm("cvt.rna.tf32.f32 %0, %1;" : "=r"(u) : "f"(f));
    return u;
}

__device__ __forceinline__ void mma8(float* c,
                                     unsigned a0, unsigned a1, unsigned a2, unsigned a3,
                                     unsigned b0, unsigned b1) {
    asm volatile(
        "mma.sync.aligned.m16n8k8.row.col.f32.tf32.tf32.f32 "
        "{%0,%1,%2,%3},{%4,%5,%6,%7},{%8,%9},{%0,%1,%2,%3};"
        : "+f"(c[0]), "+f"(c[1]), "+f"(c[2]), "+f"(c[3])
        : "r"(a0), "r"(a1), "r"(a2), "r"(a3), "r"(b0), "r"(b1));
}

// ---------------------------------------------------------------------------
// Projection GEMM (tf32 MMA, pipelined): out[m][n] = sum_d x[m][d] * W[n][d]
// M=16384, N=128, K=1024.  BM=128, BN=128, BK=16.  256 threads, 8 warps.
// ---------------------------------------------------------------------------
__global__ __launch_bounds__(256, 2) void proj_kernel(
    const float* __restrict__ x,
    const float* __restrict__ Wk,
    const float* __restrict__ Wq,
    const float* __restrict__ Wv)
{
    __shared__ unsigned Xs[128][20];
    __shared__ unsigned Ws[128][20];

    const float* W;
    float* outp;
    if (blockIdx.z == 0)      { W = Wk; outp = g_k; }
    else if (blockIdx.z == 1) { W = Wq; outp = g_q; }
    else                      { W = Wv; outp = g_v; }

    const int m0   = blockIdx.x * 128;
    const int t    = threadIdx.x;
    const int lane = t & 31;
    const int w    = t >> 5;
    const int wm   = w & 3;
    const int wn   = w >> 2;
    const int lg   = lane >> 2;
    const int lt   = lane & 3;

    const int lrow  = t >> 1;
    const int lhalf = (t & 1) * 8;

    float acc[2][8][4];
    #pragma unroll
    for (int mf = 0; mf < 2; mf++)
        #pragma unroll
        for (int j = 0; j < 8; j++)
            #pragma unroll
            for (int r = 0; r < 4; r++) acc[mf][j][r] = 0.0f;

    // prefetch k0 = 0
    float4 xa = *(const float4*)&x[(size_t)(m0 + lrow) * Dn + lhalf];
    float4 xb = *(const float4*)&x[(size_t)(m0 + lrow) * Dn + lhalf + 4];
    float4 wa = *(const float4*)&W[(size_t)lrow * Dn + lhalf];
    float4 wb = *(const float4*)&W[(size_t)lrow * Dn + lhalf + 4];

    for (int k0 = 0; k0 < Dn; k0 += 16) {
        __syncthreads();
        Xs[lrow][lhalf + 0] = f2tf(xa.x); Xs[lrow][lhalf + 2] = f2tf(xa.y);
        Xs[lrow][lhalf + 4] = f2tf(xa.z); Xs[lrow][lhalf + 6] = f2tf(xa.w);
        Xs[lrow][lhalf + 1] = f2tf(xb.x); Xs[lrow][lhalf + 3] = f2tf(xb.y);
        Xs[lrow][lhalf + 5] = f2tf(xb.z); Xs[lrow][lhalf + 7] = f2tf(xb.w);
        Ws[lrow][lhalf + 0] = f2tf(wa.x); Ws[lrow][lhalf + 2] = f2tf(wa.y);
        Ws[lrow][lhalf + 4] = f2tf(wa.z); Ws[lrow][lhalf + 6] = f2tf(wa.w);
        Ws[lrow][lhalf + 1] = f2tf(wb.x); Ws[lrow][lhalf + 3] = f2tf(wb.y);
        Ws[lrow][lhalf + 5] = f2tf(wb.z); Ws[lrow][lhalf + 7] = f2tf(wb.w);
        __syncthreads();

        if (k0 + 16 < Dn) {  // prefetch next tile while computing this one
            xa = *(const float4*)&x[(size_t)(m0 + lrow) * Dn + k0 + 16 + lhalf];
            xb = *(const float4*)&x[(size_t)(m0 + lrow) * Dn + k0 + 16 + lhalf + 4];
            wa = *(const float4*)&W[(size_t)lrow * Dn + k0 + 16 + lhalf];
            wb = *(const float4*)&W[(size_t)lrow * Dn + k0 + 16 + lhalf + 4];
        }

        #pragma unroll
        for (int ks = 0; ks < 2; ks++) {
            unsigned a[2][4];
            #pragma unroll
            for (int mf = 0; mf < 2; mf++) {
                int row = wm * 32 + mf * 16 + lg;
                uint2 a02 = *(const uint2*)&Xs[row][ks * 8 + 2 * lt];
                uint2 a13 = *(const uint2*)&Xs[row + 8][ks * 8 + 2 * lt];
                a[mf][0] = a02.x; a[mf][1] = a13.x; a[mf][2] = a02.y; a[mf][3] = a13.y;
            }
            #pragma unroll
            for (int j = 0; j < 8; j++) {
                uint2 b = *(const uint2*)&Ws[wn * 64 + j * 8 + lg][ks * 8 + 2 * lt];
                mma8(acc[0][j], a[0][0], a[0][1], a[0][2], a[0][3], b.x, b.y);
                mma8(acc[1][j], a[1][0], a[1][1], a[1][2], a[1][3], b.x, b.y);
            }
        }
    }

    #pragma unroll
    for (int mf = 0; mf < 2; mf++)
        #pragma unroll
        for (int j = 0; j < 8; j++) {
            int row = m0 + wm * 32 + mf * 16 + lg;
            int col = wn * 64 + j * 8 + 2 * lt;
            *(float2*)&outp[(size_t)row * HSn + col]       = make_float2(acc[mf][j][0], acc[mf][j][1]);
            *(float2*)&outp[(size_t)(row + 8) * HSn + col] = make_float2(acc[mf][j][2], acc[mf][j][3]);
        }
}

// ---------------------------------------------------------------------------
// Flash attention, warp-local softmax, split-K x2.
// BM=128 queries (8 warps x 16 rows), BN=64 keys/iter, 256 threads.
// grid = (Bn, 32): item = blockIdx.y -> qb = 15 - item/2, split = item&1.
// split 0: key tiles [0, qb+1), split 1: [qb+1, 2qb+2)  (both length qb+1).
// ---------------------------------------------------------------------------
#define QSTR 132    // Ks / Qstage row stride (128 permuted dims + pad)
#define VSTR 68     // Vt row stride (64 permuted keys + pad)
#define ATTN_SMEM_WORDS (64 * QSTR + 128 * VSTR)   // union also fits Qstage (128*QSTR <= this? no: 128*132=16896 > 17152? yes fits)

__global__ __launch_bounds__(256, 1) void attn_kernel()
{
    extern __shared__ unsigned sm[];
    unsigned* Ks = sm;                  // [64][QSTR]
    unsigned* Vt = sm + 64 * QSTR;      // [128][VSTR]
    unsigned* Qstage = sm;              // [128][QSTR] (prologue only, aliases Ks/Vt)

    const int b    = blockIdx.x;
    const int item = blockIdx.y;
    const int qb   = 15 - (item >> 1);
    const int sp   = item & 1;
    const int kt0  = sp ? (qb + 1) : 0;
    const int kt1  = sp ? (2 * qb + 2) : (qb + 1);

    const int t    = threadIdx.x;
    const int lane = t & 31;
    const int w    = t >> 5;
    const int lg   = lane >> 2;
    const int lt   = lane & 3;

    const float scale = 0.08838834764831845f;  // 1/sqrt(128)

    // ---- stage Q tile (scaled, tf32, pair-permuted) and read A-fragments ----
    {
        const float* qg = g_q + (size_t)(b * Tn + qb * 128) * HSn;
        #pragma unroll
        for (int it = 0; it < 16; it++) {
            int idx = it * 256 + t;           // 128*32 float4
            int r  = idx >> 5;
            int c  = (idx & 31) * 4;
            float4 v = *(const float4*)&qg[r * HSn + c];
            int g = c & ~7, off = (c & 4) ? 1 : 0;
            Qstage[r * QSTR + g + off + 0] = f2tf(v.x * scale);
            Qstage[r * QSTR + g + off + 2] = f2tf(v.y * scale);
            Qstage[r * QSTR + g + off + 4] = f2tf(v.z * scale);
            Qstage[r * QSTR + g + off + 6] = f2tf(v.w * scale);
        }
    }
    __syncthreads();

    unsigned qf[16][4];
    {
        const int qrow = w * 16 + lg;
        #pragma unroll
        for (int ks = 0; ks < 16; ks++) {
            uint2 a02 = *(const uint2*)&Qstage[qrow * QSTR + ks * 8 + 2 * lt];
            uint2 a13 = *(const uint2*)&Qstage[(qrow + 8) * QSTR + ks * 8 + 2 * lt];
            qf[ks][0] = a02.x; qf[ks][1] = a13.x; qf[ks][2] = a02.y; qf[ks][3] = a13.y;
        }
    }
    __syncthreads();   // done reading Qstage; Ks/Vt may now overwrite

    float o[16][4];
    #pragma unroll
    for (int j = 0; j < 16; j++)
        #pragma unroll
        for (int r = 0; r < 4; r++) o[j][r] = 0.0f;
    float m0 = -1e30f, m1 = -1e30f, l0 = 0.0f, l1 = 0.0f;

    const int rowg0 = qb * 128 + w * 16 + lg;   // global query rows of this thread
    const int rowg1 = rowg0 + 8;

    for (int kt = kt0; kt < kt1; kt++) {
        // ---- load K/V tiles: gmem -> regs (overlaps other warps' compute) ----
        const float* kg = g_k + (size_t)(b * Tn + kt * 64) * HSn;
        const float* vg = g_v + (size_t)(b * Tn + kt * 64) * HSn;
        float4 kr[8], vr[8];
        #pragma unroll
        for (int it = 0; it < 8; it++) {
            int idx = it * 256 + t;          // 64*32 float4
            int key = idx >> 5;
            int c   = (idx & 31) * 4;
            kr[it] = *(const float4*)&kg[key * HSn + c];
            vr[it] = *(const float4*)&vg[key * HSn + c];
        }
        __syncthreads();    // all warps done reading previous K/V
        #pragma unroll
        for (int it = 0; it < 8; it++) {
            int idx = it * 256 + t;
            int key = idx >> 5;
            int c   = (idx & 31) * 4;
            int g = c & ~7, off = (c & 4) ? 1 : 0;
            Ks[key * QSTR + g + off + 0] = f2tf(kr[it].x);
            Ks[key * QSTR + g + off + 2] = f2tf(kr[it].y);
            Ks[key * QSTR + g + off + 4] = f2tf(kr[it].z);
            Ks[key * QSTR + g + off + 6] = f2tf(kr[it].w);
            int kp = (key & ~7) | ((key & 3) << 1) | ((key & 4) >> 2);
            Vt[(c + 0) * VSTR + kp] = f2tf(vr[it].x);
            Vt[(c + 1) * VSTR + kp] = f2tf(vr[it].y);
            Vt[(c + 2) * VSTR + kp] = f2tf(vr[it].z);
            Vt[(c + 3) * VSTR + kp] = f2tf(vr[it].w);
        }
        __syncthreads();

        // ---- S = Q K^T : warp computes 16 rows x 64 keys ----
        float s[8][4];
        #pragma unroll
        for (int j = 0; j < 8; j++)
            #pragma unroll
            for (int r = 0; r < 4; r++) s[j][r] = 0.0f;

        #pragma unroll
        for (int ks = 0; ks < 16; ks++) {
            #pragma unroll
            for (int j = 0; j < 8; j++) {
                uint2 bf = *(const uint2*)&Ks[(j * 8 + lg) * QSTR + ks * 8 + 2 * lt];
                mma8(s[j], qf[ks][0], qf[ks][1], qf[ks][2], qf[ks][3], bf.x, bf.y);
            }
        }

        // ---- causal mask (only when this key tile crosses the diagonal) ----
        if (kt * 64 + 63 > qb * 128 + w * 16) {
            #pragma unroll
            for (int j = 0; j < 8; j++) {
                int col = kt * 64 + j * 8 + 2 * lt;
                if (col     > rowg0) s[j][0] = -1e30f;
                if (col + 1 > rowg0) s[j][1] = -1e30f;
                if (col     > rowg1) s[j][2] = -1e30f;
                if (col + 1 > rowg1) s[j][3] = -1e30f;
            }
        }

        // ---- warp-local online softmax (rows lg / lg+8) ----
        float mx0 = -1e30f, mx1 = -1e30f;
        #pragma unroll
        for (int j = 0; j < 8; j++) {
            mx0 = fmaxf(mx0, fmaxf(s[j][0], s[j][1]));
            mx1 = fmaxf(mx1, fmaxf(s[j][2], s[j][3]));
        }
        mx0 = fmaxf(mx0, __shfl_xor_sync(0xffffffffu, mx0, 1));
        mx0 = fmaxf(mx0, __shfl_xor_sync(0xffffffffu, mx0, 2));
        mx1 = fmaxf(mx1, __shfl_xor_sync(0xffffffffu, mx1, 1));
        mx1 = fmaxf(mx1, __shfl_xor_sync(0xffffffffu, mx1, 2));

        float mn0 = fmaxf(m0, mx0);
        float mn1 = fmaxf(m1, mx1);
        float c0 = __expf(m0 - mn0);
        float c1 = __expf(m1 - mn1);
        m0 = mn0; m1 = mn1;

        float sum0 = 0.0f, sum1 = 0.0f;
        #pragma unroll
        for (int j = 0; j < 8; j++) {
            s[j][0] = __expf(s[j][0] - mn0); sum0 += s[j][0];
            s[j][1] = __expf(s[j][1] - mn0); sum0 += s[j][1];
            s[j][2] = __expf(s[j][2] - mn1); sum1 += s[j][2];
            s[j][3] = __expf(s[j][3] - mn1); sum1 += s[j][3];
        }
        sum0 += __shfl_xor_sync(0xffffffffu, sum0, 1);
        sum0 += __shfl_xor_sync(0xffffffffu, sum0, 2);
        sum1 += __shfl_xor_sync(0xffffffffu, sum1, 1);
        sum1 += __shfl_xor_sync(0xffffffffu, sum1, 2);
        l0 = l0 * c0 + sum0;
        l1 = l1 * c1 + sum1;

        #pragma unroll
        for (int j = 0; j < 16; j++) {
            o[j][0] *= c0; o[j][1] *= c0;
            o[j][2] *= c1; o[j][3] *= c1;
        }

        // ---- C-frag -> A-frag conversion for P (shuffles, no smem) ----
        unsigned pf[8][4];
        const int src0 = (lane & ~3) | (lt >> 1);
        const int sel  = lt & 1;
        #pragma unroll
        for (int j = 0; j < 8; j++) {
            float v0 = __shfl_sync(0xffffffffu, s[j][0], src0);
            float v1 = __shfl_sync(0xffffffffu, s[j][1], src0);
            float v2 = __shfl_sync(0xffffffffu, s[j][0], src0 + 2);
            float v3 = __shfl_sync(0xffffffffu, s[j][1], src0 + 2);
            pf[j][0] = f2tf(sel ? v1 : v0);      // P[lg][8j+lt]
            pf[j][2] = f2tf(sel ? v3 : v2);      // P[lg][8j+lt+4]
            float u0 = __shfl_sync(0xffffffffu, s[j][2], src0);
            float u1 = __shfl_sync(0xffffffffu, s[j][3], src0);
            float u2 = __shfl_sync(0xffffffffu, s[j][2], src0 + 2);
            float u3 = __shfl_sync(0xffffffffu, s[j][3], src0 + 2);
            pf[j][1] = f2tf(sel ? u1 : u0);      // P[lg+8][8j+lt]
            pf[j][3] = f2tf(sel ? u3 : u2);      // P[lg+8][8j+lt+4]
        }

        // ---- O += P V  (A = pf, B = Vt) ----
        #pragma unroll
        for (int g = 0; g < 8; g++) {
            #pragma unroll
            for (int j2 = 0; j2 < 16; j2++) {
                uint2 bf = *(const uint2*)&Vt[(j2 * 8 + lg) * VSTR + g * 8 + 2 * lt];
                mma8(o[j2], pf[g][0], pf[g][1], pf[g][2], pf[g][3], bf.x, bf.y);
            }
        }
    }

    // ---- write partials (unnormalized O + m + l) ----
    {
        float* po = g_po + (size_t)sp * (Bn * Tn * HSn);
        size_t r0 = (size_t)(b * Tn) + rowg0;
        size_t r1 = (size_t)(b * Tn) + rowg1;
        #pragma unroll
        for (int j2 = 0; j2 < 16; j2++) {
            int col = j2 * 8 + 2 * lt;
            *(float2*)&po[r0 * HSn + col] = make_float2(o[j2][0], o[j2][1]);
            *(float2*)&po[r1 * HSn + col] = make_float2(o[j2][2], o[j2][3]);
        }
        if (lt == 0) {
            g_pm[sp * (Bn * Tn) + r0] = m0;
            g_pl[sp * (Bn * Tn) + r0] = l0;
            g_pm[sp * (Bn * Tn) + r1] = m1;
            g_pl[sp * (Bn * Tn) + r1] = l1;
        }
    }
}

// ---------------------------------------------------------------------------
// Merge the two split-K partials.
// ---------------------------------------------------------------------------
__global__ __launch_bounds__(256) void merge_kernel(float* __restrict__ out)
{
    int i4 = blockIdx.x * 256 + threadIdx.x;      // float4 index
    int row = i4 >> 5;                            // 32 float4 per row
    float m0 = g_pm[row], m1 = g_pm[Bn * Tn + row];
    float l0 = g_pl[row], l1 = g_pl[Bn * Tn + row];
    float m  = fmaxf(m0, m1);
    float w0 = __expf(m0 - m);
    float w1 = __expf(m1 - m);
    float inv = 1.0f / (l0 * w0 + l1 * w1);
    const float4 a = *(const float4*)&g_po[(size_t)i4 * 4];
    const float4 c = *(const float4*)&g_po[(size_t)(Bn * Tn * HSn) + (size_t)i4 * 4];
    float4 r;
    r.x = (a.x * w0 + c.x * w1) * inv;
    r.y = (a.y * w0 + c.y * w1) * inv;
    r.z = (a.z * w0 + c.z * w1) * inv;
    r.w = (a.w * w0 + c.w * w1) * inv;
    *(float4*)&out[(size_t)i4 * 4] = r;
}

// ---------------------------------------------------------------------------
extern "C" void kernel_launch(void* const* d_in, const int* in_sizes, int n_in,
                              void* d_out, int out_size)
{
    const float* x  = (const float*)d_in[0];
    const float* Wk = (const float*)d_in[1];
    const float* Wq = (const float*)d_in[2];
    const float* Wv = (const float*)d_in[3];
    float* out = (float*)d_out;

    dim3 pg(Bn * Tn / 128, 1, 3);
    proj_kernel<<<pg, 256>>>(x, Wk, Wq, Wv);

    const int smem_bytes = ATTN_SMEM_WORDS * (int)sizeof(unsigned);
    cudaFuncSetAttribute(attn_kernel, cudaFuncAttributeMaxDynamicSharedMemorySize, smem_bytes);
    dim3 ag(Bn, 32);   // grid.y = work item (heaviest first), grid.x = batch
    attn_kernel<<<ag, 256, smem_bytes>>>();

    merge_kernel<<<(Bn * Tn * HSn / 4) / 256, 256>>>(out);
}

// round 4
// speedup vs baseline: 3.3354x; 1.0603x over previous
#include <cuda_runtime.h>

#define Bn  8
#define Tn  2048
#define Dn  1024
#define HSn 128

// g_k: [B][T][HS] tf32 bits, dims pair-permuted.
// g_q: [B][T][HS] tf32 bits, pre-scaled by 1/sqrt(HS), dims pair-permuted.
// g_v: [B][HS][T] tf32 bits (transposed), tokens pair-permuted within 8-groups.
__device__ float g_k[Bn * Tn * HSn];
__device__ float g_q[Bn * Tn * HSn];
__device__ float g_v[Bn * Tn * HSn];
__device__ float g_po[2 * Bn * Tn * HSn];
__device__ float g_pm[2 * Bn * Tn];
__device__ float g_pl[2 * Bn * Tn];

__device__ __forceinline__ unsigned f2tf(float f) {
    unsigned u;
    asm("cvt.rna.tf32.f32 %0, %1;" : "=r"(u) : "f"(f));
    return u;
}

__device__ __forceinline__ void mma8(float* c,
                                     unsigned a0, unsigned a1, unsigned a2, unsigned a3,
                                     unsigned b0, unsigned b1) {
    asm volatile(
        "mma.sync.aligned.m16n8k8.row.col.f32.tf32.tf32.f32 "
        "{%0,%1,%2,%3},{%4,%5,%6,%7},{%8,%9},{%0,%1,%2,%3};"
        : "+f"(c[0]), "+f"(c[1]), "+f"(c[2]), "+f"(c[3])
        : "r"(a0), "r"(a1), "r"(a2), "r"(a3), "r"(b0), "r"(b1));
}

// pair-permute within 8-group: value for index d lives at slot PERM(d)
__device__ __host__ __forceinline__ int PERM(int d) {
    return (d & ~7) | ((d & 3) << 1) | ((d & 4) >> 2);
}

__device__ __forceinline__ void cpa16(void* smem_ptr, const void* gptr) {
    unsigned saddr = (unsigned)__cvta_generic_to_shared(smem_ptr);
    asm volatile("cp.async.cg.shared.global [%0], [%1], 16;\n" :: "r"(saddr), "l"(gptr));
}

// ---------------------------------------------------------------------------
// Projection GEMM (tf32 MMA, 2-stage double-buffered smem).
// M=16384, N=128, K=1024. BM=128, BN=128, BK=16. 256 threads, 8 warps (4m x 2n).
// z: 0 -> g_k (perm dims), 1 -> g_q (scaled, perm dims), 2 -> g_v (transposed).
// ---------------------------------------------------------------------------
#define PXW 20

__device__ __forceinline__ void proj_sts(unsigned* Xs, unsigned* Ws,
                                         int lrow, int lhalf,
                                         const float4& xa, const float4& xb,
                                         const float4& wa, const float4& wb) {
    Xs[lrow * PXW + lhalf + 0] = f2tf(xa.x); Xs[lrow * PXW + lhalf + 2] = f2tf(xa.y);
    Xs[lrow * PXW + lhalf + 4] = f2tf(xa.z); Xs[lrow * PXW + lhalf + 6] = f2tf(xa.w);
    Xs[lrow * PXW + lhalf + 1] = f2tf(xb.x); Xs[lrow * PXW + lhalf + 3] = f2tf(xb.y);
    Xs[lrow * PXW + lhalf + 5] = f2tf(xb.z); Xs[lrow * PXW + lhalf + 7] = f2tf(xb.w);
    Ws[lrow * PXW + lhalf + 0] = f2tf(wa.x); Ws[lrow * PXW + lhalf + 2] = f2tf(wa.y);
    Ws[lrow * PXW + lhalf + 4] = f2tf(wa.z); Ws[lrow * PXW + lhalf + 6] = f2tf(wa.w);
    Ws[lrow * PXW + lhalf + 1] = f2tf(wb.x); Ws[lrow * PXW + lhalf + 3] = f2tf(wb.y);
    Ws[lrow * PXW + lhalf + 5] = f2tf(wb.z); Ws[lrow * PXW + lhalf + 7] = f2tf(wb.w);
}

__device__ __forceinline__ void proj_mma(const unsigned* Xs, const unsigned* Ws,
                                         float acc[2][8][4],
                                         int wm, int wn, int lg, int lt) {
    #pragma unroll
    for (int ks = 0; ks < 2; ks++) {
        unsigned a[2][4];
        #pragma unroll
        for (int mf = 0; mf < 2; mf++) {
            int row = wm * 32 + mf * 16 + lg;
            uint2 a02 = *(const uint2*)&Xs[row * PXW + ks * 8 + 2 * lt];
            uint2 a13 = *(const uint2*)&Xs[(row + 8) * PXW + ks * 8 + 2 * lt];
            a[mf][0] = a02.x; a[mf][1] = a13.x; a[mf][2] = a02.y; a[mf][3] = a13.y;
        }
        #pragma unroll
        for (int j = 0; j < 8; j++) {
            uint2 b = *(const uint2*)&Ws[(wn * 64 + j * 8 + lg) * PXW + ks * 8 + 2 * lt];
            mma8(acc[0][j], a[0][0], a[0][1], a[0][2], a[0][3], b.x, b.y);
            mma8(acc[1][j], a[1][0], a[1][1], a[1][2], a[1][3], b.x, b.y);
        }
    }
}

__global__ __launch_bounds__(256, 2) void proj_kernel(
    const float* __restrict__ x,
    const float* __restrict__ Wk,
    const float* __restrict__ Wq,
    const float* __restrict__ Wv)
{
    __shared__ unsigned Xs[2][128 * PXW];
    __shared__ unsigned Ws[2][128 * PXW];

    const int z = blockIdx.z;
    const float* W = (z == 0) ? Wk : (z == 1) ? Wq : Wv;

    const int m0   = blockIdx.x * 128;
    const int t    = threadIdx.x;
    const int lane = t & 31;
    const int w    = t >> 5;
    const int wm   = w & 3;
    const int wn   = w >> 2;
    const int lg   = lane >> 2;
    const int lt   = lane & 3;

    const int lrow  = t >> 1;
    const int lhalf = (t & 1) * 8;

    const float* xrow = x + (size_t)(m0 + lrow) * Dn + lhalf;
    const float* wrow = W + (size_t)lrow * Dn + lhalf;

    float acc[2][8][4];
    #pragma unroll
    for (int mf = 0; mf < 2; mf++)
        #pragma unroll
        for (int j = 0; j < 8; j++)
            #pragma unroll
            for (int r = 0; r < 4; r++) acc[mf][j][r] = 0.0f;

    // prologue: load tile0 -> STS stage0 -> load tile1
    float4 xa = *(const float4*)(xrow);
    float4 xb = *(const float4*)(xrow + 4);
    float4 wa = *(const float4*)(wrow);
    float4 wb = *(const float4*)(wrow + 4);
    proj_sts(Xs[0], Ws[0], lrow, lhalf, xa, xb, wa, wb);
    xa = *(const float4*)(xrow + 16);
    xb = *(const float4*)(xrow + 20);
    wa = *(const float4*)(wrow + 16);
    wb = *(const float4*)(wrow + 20);

    const int NIT = Dn / 16;   // 64
    for (int i = 0; i < NIT; i++) {
        __syncthreads();
        if (i + 1 < NIT)
            proj_sts(Xs[(i + 1) & 1], Ws[(i + 1) & 1], lrow, lhalf, xa, xb, wa, wb);
        if (i + 2 < NIT) {
            xa = *(const float4*)(xrow + (i + 2) * 16);
            xb = *(const float4*)(xrow + (i + 2) * 16 + 4);
            wa = *(const float4*)(wrow + (i + 2) * 16);
            wb = *(const float4*)(wrow + (i + 2) * 16 + 4);
        }
        proj_mma(Xs[i & 1], Ws[i & 1], acc, wm, wn, lg, lt);
    }

    const float qscale = 0.08838834764831845f;   // 1/sqrt(128)
    #pragma unroll
    for (int mf = 0; mf < 2; mf++)
        #pragma unroll
        for (int j = 0; j < 8; j++) {
            int row = m0 + wm * 32 + mf * 16 + lg;
            int c   = wn * 64 + j * 8 + 2 * lt;
            float v00 = acc[mf][j][0], v01 = acc[mf][j][1];
            float v10 = acc[mf][j][2], v11 = acc[mf][j][3];
            if (z == 0) {
                g_k[(size_t)row * HSn + PERM(c)]           = __uint_as_float(f2tf(v00));
                g_k[(size_t)row * HSn + PERM(c + 1)]       = __uint_as_float(f2tf(v01));
                g_k[(size_t)(row + 8) * HSn + PERM(c)]     = __uint_as_float(f2tf(v10));
                g_k[(size_t)(row + 8) * HSn + PERM(c + 1)] = __uint_as_float(f2tf(v11));
            } else if (z == 1) {
                g_q[(size_t)row * HSn + PERM(c)]           = __uint_as_float(f2tf(v00 * qscale));
                g_q[(size_t)row * HSn + PERM(c + 1)]       = __uint_as_float(f2tf(v01 * qscale));
                g_q[(size_t)(row + 8) * HSn + PERM(c)]     = __uint_as_float(f2tf(v10 * qscale));
                g_q[(size_t)(row + 8) * HSn + PERM(c + 1)] = __uint_as_float(f2tf(v11 * qscale));
            } else {
                int bb   = row >> 11;
                int tok  = row & 2047;
                int tokp = PERM(tok);           // row+8 -> tokp+8 (same low-3 bits)
                size_t base0 = ((size_t)bb * HSn + c) * Tn;
                size_t base1 = ((size_t)bb * HSn + c + 1) * Tn;
                g_v[base0 + tokp]     = __uint_as_float(f2tf(v00));
                g_v[base1 + tokp]     = __uint_as_float(f2tf(v01));
                g_v[base0 + tokp + 8] = __uint_as_float(f2tf(v10));
                g_v[base1 + tokp + 8] = __uint_as_float(f2tf(v11));
            }
        }
}

// ---------------------------------------------------------------------------
// Flash attention: BM=128 q (8 warps x 16 rows), BN=64 keys/iter, split-K x2.
// K/V tiles via cp.async, 2-stage double buffer. All data pre-tf32/permuted.
// ---------------------------------------------------------------------------
#define QSTR 132
#define KSTR 132
#define VSTR 68
#define KWORDS (64 * KSTR)                  // 8448
#define STGW  (KWORDS + 128 * VSTR)         // 17152
#define ATTN_SMEM_BYTES (2 * STGW * 4)      // 137216

__device__ __forceinline__ void attn_issue(unsigned* stage, const float* kg,
                                           const float* vg, int t) {
    unsigned* Ks = stage;
    unsigned* Vt = stage + KWORDS;
    #pragma unroll
    for (int ch = 0; ch < 8; ch++) {
        int idx = ch * 256 + t;
        int key = idx >> 5;
        int c4  = idx & 31;
        cpa16(&Ks[key * KSTR + c4 * 4], (const uint4*)(kg + (size_t)key * HSn) + c4);
    }
    #pragma unroll
    for (int ch = 0; ch < 8; ch++) {
        int idx = ch * 256 + t;
        int dim = idx >> 4;
        int k4  = idx & 15;
        cpa16(&Vt[dim * VSTR + k4 * 4], (const uint4*)(vg + (size_t)dim * Tn) + k4);
    }
    asm volatile("cp.async.commit_group;\n" ::);
}

__global__ __launch_bounds__(256) void attn_kernel()
{
    extern __shared__ unsigned sm[];
    unsigned* Qstage = sm;   // prologue-only alias of stage buffers

    const int b    = blockIdx.x;
    const int item = blockIdx.y;
    const int qb   = 15 - (item >> 1);
    const int sp   = item & 1;
    const int kt0  = sp ? (qb + 1) : 0;
    const int nk   = qb + 1;                 // both splits: qb+1 tiles

    const int t    = threadIdx.x;
    const int lane = t & 31;
    const int w    = t >> 5;
    const int lg   = lane >> 2;
    const int lt   = lane & 3;

    // ---- stage Q (raw tf32-permuted copy) and read A-fragments ----
    {
        const uint4* qg = (const uint4*)(g_q + (size_t)(b * Tn + qb * 128) * HSn);
        #pragma unroll
        for (int it = 0; it < 16; it++) {
            int idx = it * 256 + t;
            int r   = idx >> 5;
            int c4  = idx & 31;
            *(uint4*)&Qstage[r * QSTR + c4 * 4] = qg[r * 32 + c4];
        }
    }
    __syncthreads();

    unsigned qf[16][4];
    {
        const int qrow = w * 16 + lg;
        #pragma unroll
        for (int ks = 0; ks < 16; ks++) {
            uint2 a02 = *(const uint2*)&Qstage[qrow * QSTR + ks * 8 + 2 * lt];
            uint2 a13 = *(const uint2*)&Qstage[(qrow + 8) * QSTR + ks * 8 + 2 * lt];
            qf[ks][0] = a02.x; qf[ks][1] = a13.x; qf[ks][2] = a02.y; qf[ks][3] = a13.y;
        }
    }
    __syncthreads();   // Q reads done; stage buffers may be overwritten

    float o[16][4];
    #pragma unroll
    for (int j = 0; j < 16; j++)
        #pragma unroll
        for (int r = 0; r < 4; r++) o[j][r] = 0.0f;
    float m0 = -1e30f, m1 = -1e30f, l0 = 0.0f, l1 = 0.0f;

    const int rowg0 = qb * 128 + w * 16 + lg;
    const int rowg1 = rowg0 + 8;

    const float* kbase = g_k + (size_t)b * Tn * HSn;
    const float* vbase = g_v + (size_t)b * HSn * Tn;

    attn_issue(sm, kbase + (size_t)(kt0) * 64 * HSn, vbase + kt0 * 64, t);

    for (int ii = 0; ii < nk; ii++) {
        const int kt = kt0 + ii;
        if (ii + 1 < nk) {
            attn_issue(sm + ((ii + 1) & 1) * STGW,
                       kbase + (size_t)(kt + 1) * 64 * HSn, vbase + (kt + 1) * 64, t);
            asm volatile("cp.async.wait_group 1;\n" ::);
        } else {
            asm volatile("cp.async.wait_group 0;\n" ::);
        }
        __syncthreads();

        const unsigned* Ks = sm + (ii & 1) * STGW;
        const unsigned* Vt = Ks + KWORDS;

        // ---- S = Q K^T ----
        float s[8][4];
        #pragma unroll
        for (int j = 0; j < 8; j++)
            #pragma unroll
            for (int r = 0; r < 4; r++) s[j][r] = 0.0f;

        #pragma unroll
        for (int ks = 0; ks < 16; ks++) {
            #pragma unroll
            for (int j = 0; j < 8; j++) {
                uint2 bf = *(const uint2*)&Ks[(j * 8 + lg) * KSTR + ks * 8 + 2 * lt];
                mma8(s[j], qf[ks][0], qf[ks][1], qf[ks][2], qf[ks][3], bf.x, bf.y);
            }
        }

        // ---- causal mask ----
        if (kt * 64 + 63 > qb * 128 + w * 16) {
            #pragma unroll
            for (int j = 0; j < 8; j++) {
                int col = kt * 64 + j * 8 + 2 * lt;
                if (col     > rowg0) s[j][0] = -1e30f;
                if (col + 1 > rowg0) s[j][1] = -1e30f;
                if (col     > rowg1) s[j][2] = -1e30f;
                if (col + 1 > rowg1) s[j][3] = -1e30f;
            }
        }

        // ---- warp-local online softmax ----
        float mx0 = -1e30f, mx1 = -1e30f;
        #pragma unroll
        for (int j = 0; j < 8; j++) {
            mx0 = fmaxf(mx0, fmaxf(s[j][0], s[j][1]));
            mx1 = fmaxf(mx1, fmaxf(s[j][2], s[j][3]));
        }
        mx0 = fmaxf(mx0, __shfl_xor_sync(0xffffffffu, mx0, 1));
        mx0 = fmaxf(mx0, __shfl_xor_sync(0xffffffffu, mx0, 2));
        mx1 = fmaxf(mx1, __shfl_xor_sync(0xffffffffu, mx1, 1));
        mx1 = fmaxf(mx1, __shfl_xor_sync(0xffffffffu, mx1, 2));

        float mn0 = fmaxf(m0, mx0);
        float mn1 = fmaxf(m1, mx1);
        float c0 = __expf(m0 - mn0);
        float c1 = __expf(m1 - mn1);
        m0 = mn0; m1 = mn1;

        float sum0 = 0.0f, sum1 = 0.0f;
        #pragma unroll
        for (int j = 0; j < 8; j++) {
            s[j][0] = __expf(s[j][0] - mn0); sum0 += s[j][0];
            s[j][1] = __expf(s[j][1] - mn0); sum0 += s[j][1];
            s[j][2] = __expf(s[j][2] - mn1); sum1 += s[j][2];
            s[j][3] = __expf(s[j][3] - mn1); sum1 += s[j][3];
        }
        sum0 += __shfl_xor_sync(0xffffffffu, sum0, 1);
        sum0 += __shfl_xor_sync(0xffffffffu, sum0, 2);
        sum1 += __shfl_xor_sync(0xffffffffu, sum1, 1);
        sum1 += __shfl_xor_sync(0xffffffffu, sum1, 2);
        l0 = l0 * c0 + sum0;
        l1 = l1 * c1 + sum1;

        #pragma unroll
        for (int j = 0; j < 16; j++) {
            o[j][0] *= c0; o[j][1] *= c0;
            o[j][2] *= c1; o[j][3] *= c1;
        }

        // ---- C-frag -> A-frag for P (shuffles) ----
        unsigned pf[8][4];
        const int src0 = (lane & ~3) | (lt >> 1);
        const int sel  = lt & 1;
        #pragma unroll
        for (int j = 0; j < 8; j++) {
            float v0 = __shfl_sync(0xffffffffu, s[j][0], src0);
            float v1 = __shfl_sync(0xffffffffu, s[j][1], src0);
            float v2 = __shfl_sync(0xffffffffu, s[j][0], src0 + 2);
            float v3 = __shfl_sync(0xffffffffu, s[j][1], src0 + 2);
            pf[j][0] = f2tf(sel ? v1 : v0);
            pf[j][2] = f2tf(sel ? v3 : v2);
            float u0 = __shfl_sync(0xffffffffu, s[j][2], src0);
            float u1 = __shfl_sync(0xffffffffu, s[j][3], src0);
            float u2 = __shfl_sync(0xffffffffu, s[j][2], src0 + 2);
            float u3 = __shfl_sync(0xffffffffu, s[j][3], src0 + 2);
            pf[j][1] = f2tf(sel ? u1 : u0);
            pf[j][3] = f2tf(sel ? u3 : u2);
        }

        // ---- O += P V ----
        #pragma unroll
        for (int g = 0; g < 8; g++) {
            #pragma unroll
            for (int j2 = 0; j2 < 16; j2++) {
                uint2 bf = *(const uint2*)&Vt[(j2 * 8 + lg) * VSTR + g * 8 + 2 * lt];
                mma8(o[j2], pf[g][0], pf[g][1], pf[g][2], pf[g][3], bf.x, bf.y);
            }
        }
        __syncthreads();
    }

    // ---- write partials ----
    {
        float* po = g_po + (size_t)sp * (Bn * Tn * HSn);
        size_t r0 = (size_t)(b * Tn) + rowg0;
        size_t r1 = (size_t)(b * Tn) + rowg1;
        #pragma unroll
        for (int j2 = 0; j2 < 16; j2++) {
            int col = j2 * 8 + 2 * lt;
            *(float2*)&po[r0 * HSn + col] = make_float2(o[j2][0], o[j2][1]);
            *(float2*)&po[r1 * HSn + col] = make_float2(o[j2][2], o[j2][3]);
        }
        if (lt == 0) {
            g_pm[sp * (Bn * Tn) + r0] = m0;
            g_pl[sp * (Bn * Tn) + r0] = l0;
            g_pm[sp * (Bn * Tn) + r1] = m1;
            g_pl[sp * (Bn * Tn) + r1] = l1;
        }
    }
}

// ---------------------------------------------------------------------------
__global__ __launch_bounds__(256) void merge_kernel(float* __restrict__ out)
{
    int i4 = blockIdx.x * 256 + threadIdx.x;
    int row = i4 >> 5;
    float m0 = g_pm[row], m1 = g_pm[Bn * Tn + row];
    float l0 = g_pl[row], l1 = g_pl[Bn * Tn + row];
    float m  = fmaxf(m0, m1);
    float w0 = __expf(m0 - m);
    float w1 = __expf(m1 - m);
    float inv = 1.0f / (l0 * w0 + l1 * w1);
    const float4 a = *(const float4*)&g_po[(size_t)i4 * 4];
    const float4 c = *(const float4*)&g_po[(size_t)(Bn * Tn * HSn) + (size_t)i4 * 4];
    float4 r;
    r.x = (a.x * w0 + c.x * w1) * inv;
    r.y = (a.y * w0 + c.y * w1) * inv;
    r.z = (a.z * w0 + c.z * w1) * inv;
    r.w = (a.w * w0 + c.w * w1) * inv;
    *(float4*)&out[(size_t)i4 * 4] = r;
}

// ---------------------------------------------------------------------------
extern "C" void kernel_launch(void* const* d_in, const int* in_sizes, int n_in,
                              void* d_out, int out_size)
{
    const float* x  = (const float*)d_in[0];
    const float* Wk = (const float*)d_in[1];
    const float* Wq = (const float*)d_in[2];
    const float* Wv = (const float*)d_in[3];
    float* out = (float*)d_out;

    dim3 pg(Bn * Tn / 128, 1, 3);
    proj_kernel<<<pg, 256>>>(x, Wk, Wq, Wv);

    cudaFuncSetAttribute(attn_kernel, cudaFuncAttributeMaxDynamicSharedMemorySize,
                         ATTN_SMEM_BYTES);
    dim3 ag(Bn, 32);
    attn_kernel<<<ag, 256, ATTN_SMEM_BYTES>>>();

    merge_kernel<<<(Bn * Tn * HSn / 4) / 256, 256>>>(out);
}

// round 5
// speedup vs baseline: 7.8942x; 2.3668x over previous
#include <cuda_runtime.h>
#include <cuda_fp16.h>

#define Bn  8
#define Tn  2048
#define Dn  1024
#define HSn 128

// Projected tensors, fp16, natural [B][T][HS] layout.
__device__ __half g_k[Bn * Tn * HSn];
__device__ __half g_q[Bn * Tn * HSn];   // pre-scaled by 1/sqrt(HS)
__device__ __half g_v[Bn * Tn * HSn];
__device__ float  g_po[2 * Bn * Tn * HSn];
__device__ float  g_pm[2 * Bn * Tn];
__device__ float  g_pl[2 * Bn * Tn];

// pack two fp32 -> f16x2 (lo = first arg)
__device__ __forceinline__ unsigned packh2(float lo, float hi) {
    unsigned r;
    asm("cvt.rn.f16x2.f32 %0, %1, %2;" : "=r"(r) : "f"(hi), "f"(lo));
    return r;
}

// mma m16n8k16 fp16 inputs, fp32 accum
__device__ __forceinline__ void mma16(float* c, const unsigned* a,
                                      unsigned b0, unsigned b1) {
    asm volatile(
        "mma.sync.aligned.m16n8k16.row.col.f32.f16.f16.f32 "
        "{%0,%1,%2,%3},{%4,%5,%6,%7},{%8,%9},{%0,%1,%2,%3};"
        : "+f"(c[0]), "+f"(c[1]), "+f"(c[2]), "+f"(c[3])
        : "r"(a[0]), "r"(a[1]), "r"(a[2]), "r"(a[3]), "r"(b0), "r"(b1));
}

__device__ __forceinline__ void ldsm4(unsigned* r, const void* p) {
    unsigned a = (unsigned)__cvta_generic_to_shared(p);
    asm volatile("ldmatrix.sync.aligned.m8n8.x4.shared.b16 {%0,%1,%2,%3}, [%4];"
                 : "=r"(r[0]), "=r"(r[1]), "=r"(r[2]), "=r"(r[3]) : "r"(a));
}

__device__ __forceinline__ void ldsm4t(unsigned* r, const void* p) {
    unsigned a = (unsigned)__cvta_generic_to_shared(p);
    asm volatile("ldmatrix.sync.aligned.m8n8.x4.trans.shared.b16 {%0,%1,%2,%3}, [%4];"
                 : "=r"(r[0]), "=r"(r[1]), "=r"(r[2]), "=r"(r[3]) : "r"(a));
}

__device__ __forceinline__ void cpa16(void* smem_ptr, const void* gptr) {
    unsigned saddr = (unsigned)__cvta_generic_to_shared(smem_ptr);
    asm volatile("cp.async.cg.shared.global [%0], [%1], 16;\n" :: "r"(saddr), "l"(gptr));
}

// ---------------------------------------------------------------------------
// Projection GEMM (fp16 MMA): out[m][n] = sum_d x[m][d] * W[n][d]
// M=16384, N=128, K=1024. BM=128, BN=128, BK=32. 256 threads, 8 warps (4m x 2n).
// smem row stride 40 halfs (80B = 5x16B units -> LDSM conflict-free).
// ---------------------------------------------------------------------------
#define PST 40

__device__ __forceinline__ void proj_sts(__half* Xs, __half* Ws, int row, int cb,
    const float4& xa, const float4& xb, const float4& xc, const float4& xd,
    const float4& wa, const float4& wb, const float4& wc, const float4& wd)
{
    uint4 u;
    u.x = packh2(xa.x, xa.y); u.y = packh2(xa.z, xa.w);
    u.z = packh2(xb.x, xb.y); u.w = packh2(xb.z, xb.w);
    *(uint4*)&Xs[row * PST + cb] = u;
    u.x = packh2(xc.x, xc.y); u.y = packh2(xc.z, xc.w);
    u.z = packh2(xd.x, xd.y); u.w = packh2(xd.z, xd.w);
    *(uint4*)&Xs[row * PST + cb + 8] = u;
    u.x = packh2(wa.x, wa.y); u.y = packh2(wa.z, wa.w);
    u.z = packh2(wb.x, wb.y); u.w = packh2(wb.z, wb.w);
    *(uint4*)&Ws[row * PST + cb] = u;
    u.x = packh2(wc.x, wc.y); u.y = packh2(wc.z, wc.w);
    u.z = packh2(wd.x, wd.y); u.w = packh2(wd.z, wd.w);
    *(uint4*)&Ws[row * PST + cb + 8] = u;
}

__device__ __forceinline__ void proj_mma(const __half* Xs, const __half* Ws,
                                         float acc[2][8][4],
                                         int wm, int wn, int lane)
{
    const int arow = wm * 32 + (lane & 15);          // + mf*16
    const int ach  = (lane >> 4) * 8;                // col-half select
    const int brow = wn * 64 + (lane & 7) + (lane >> 4) * 8;  // + jp*16
    const int bch  = ((lane >> 3) & 1) * 8;
    #pragma unroll
    for (int ks = 0; ks < 2; ks++) {
        unsigned af[2][4];
        ldsm4(af[0], &Xs[arow * PST + ks * 16 + ach]);
        ldsm4(af[1], &Xs[(arow + 16) * PST + ks * 16 + ach]);
        #pragma unroll
        for (int jp = 0; jp < 4; jp++) {
            unsigned bf[4];
            ldsm4(bf, &Ws[(brow + jp * 16) * PST + ks * 16 + bch]);
            mma16(acc[0][2 * jp],     af[0], bf[0], bf[1]);
            mma16(acc[1][2 * jp],     af[1], bf[0], bf[1]);
            mma16(acc[0][2 * jp + 1], af[0], bf[2], bf[3]);
            mma16(acc[1][2 * jp + 1], af[1], bf[2], bf[3]);
        }
    }
}

__global__ __launch_bounds__(256, 2) void proj_kernel(
    const float* __restrict__ x,
    const float* __restrict__ Wk,
    const float* __restrict__ Wq,
    const float* __restrict__ Wv)
{
    __shared__ __half Xs[2][128 * PST];
    __shared__ __half Ws[2][128 * PST];

    const int z = blockIdx.z;
    const float* W = (z == 0) ? Wk : (z == 1) ? Wq : Wv;

    const int m0   = blockIdx.x * 128;
    const int t    = threadIdx.x;
    const int lane = t & 31;
    const int w    = t >> 5;
    const int wm   = w & 3;
    const int wn   = w >> 2;
    const int lg   = lane >> 2;
    const int lt   = lane & 3;

    const int lrow = t >> 1;           // 0..127
    const int lcb  = (t & 1) * 16;     // col base 0 or 16

    const float* xrow = x + (size_t)(m0 + lrow) * Dn + lcb;
    const float* wrow = W + (size_t)lrow * Dn + lcb;

    float acc[2][8][4];
    #pragma unroll
    for (int mf = 0; mf < 2; mf++)
        #pragma unroll
        for (int j = 0; j < 8; j++)
            #pragma unroll
            for (int r = 0; r < 4; r++) acc[mf][j][r] = 0.0f;

    float4 xa = *(const float4*)(xrow);
    float4 xb = *(const float4*)(xrow + 4);
    float4 xc = *(const float4*)(xrow + 8);
    float4 xd = *(const float4*)(xrow + 12);
    float4 wa = *(const float4*)(wrow);
    float4 wb = *(const float4*)(wrow + 4);
    float4 wc = *(const float4*)(wrow + 8);
    float4 wd = *(const float4*)(wrow + 12);
    proj_sts(Xs[0], Ws[0], lrow, lcb, xa, xb, xc, xd, wa, wb, wc, wd);
    xa = *(const float4*)(xrow + 32); xb = *(const float4*)(xrow + 36);
    xc = *(const float4*)(xrow + 40); xd = *(const float4*)(xrow + 44);
    wa = *(const float4*)(wrow + 32); wb = *(const float4*)(wrow + 36);
    wc = *(const float4*)(wrow + 40); wd = *(const float4*)(wrow + 44);

    const int NIT = Dn / 32;   // 32
    for (int i = 0; i < NIT; i++) {
        __syncthreads();
        if (i + 1 < NIT)
            proj_sts(Xs[(i + 1) & 1], Ws[(i + 1) & 1], lrow, lcb,
                     xa, xb, xc, xd, wa, wb, wc, wd);
        if (i + 2 < NIT) {
            const float* xp = xrow + (i + 2) * 32;
            const float* wp = wrow + (i + 2) * 32;
            xa = *(const float4*)(xp);      xb = *(const float4*)(xp + 4);
            xc = *(const float4*)(xp + 8);  xd = *(const float4*)(xp + 12);
            wa = *(const float4*)(wp);      wb = *(const float4*)(wp + 4);
            wc = *(const float4*)(wp + 8);  wd = *(const float4*)(wp + 12);
        }
        proj_mma(Xs[i & 1], Ws[i & 1], acc, wm, wn, lane);
    }

    __half* dst = (z == 0) ? g_k : (z == 1) ? g_q : g_v;
    const float qscale = (z == 1) ? 0.08838834764831845f : 1.0f;
    #pragma unroll
    for (int mf = 0; mf < 2; mf++)
        #pragma unroll
        for (int j = 0; j < 8; j++) {
            int row = m0 + wm * 32 + mf * 16 + lg;
            int col = wn * 64 + j * 8 + 2 * lt;
            *(unsigned*)&dst[(size_t)row * HSn + col] =
                packh2(acc[mf][j][0] * qscale, acc[mf][j][1] * qscale);
            *(unsigned*)&dst[(size_t)(row + 8) * HSn + col] =
                packh2(acc[mf][j][2] * qscale, acc[mf][j][3] * qscale);
        }
}

// ---------------------------------------------------------------------------
// Flash attention, fp16 MMA. BM=128 q (8 warps x 16 rows), BN=64 keys/iter.
// Split-K x2, cp.async double-buffered K/V, LDSM fragments, V via ldmatrix.trans.
// smem row stride 136 halfs (272B = 17x16B units -> LDSM conflict-free).
// ---------------------------------------------------------------------------
#define AST 136
#define KHALF (64 * AST)            // 8704 halfs per K (or V) tile
#define STGH  (2 * KHALF)           // 17408 halfs per stage
#define ATTN_SMEM_BYTES (2 * STGH * 2)   // 69632 B

__device__ __forceinline__ void attn_issue(__half* stage, const __half* kg,
                                           const __half* vg, int t) {
    __half* Ks = stage;
    __half* Vs = stage + KHALF;
    #pragma unroll
    for (int ch = 0; ch < 4; ch++) {
        int idx = ch * 256 + t;
        int r = idx >> 4;
        int c = (idx & 15) * 8;
        cpa16(&Ks[r * AST + c], kg + (size_t)r * HSn + c);
        cpa16(&Vs[r * AST + c], vg + (size_t)r * HSn + c);
    }
    asm volatile("cp.async.commit_group;\n" ::);
}

__global__ __launch_bounds__(256) void attn_kernel()
{
    extern __shared__ __half smh[];

    const int b    = blockIdx.x;
    const int item = blockIdx.y;
    const int qb   = 15 - (item >> 1);
    const int sp   = item & 1;
    const int kt0  = sp ? (qb + 1) : 0;
    const int nk   = qb + 1;

    const int t    = threadIdx.x;
    const int lane = t & 31;
    const int w    = t >> 5;
    const int lg   = lane >> 2;
    const int lt   = lane & 3;

    // ---- stage Q tile (fp16, raw copy) into stage-0 region, read A-frags ----
    {
        const uint4* qg = (const uint4*)(g_q + (size_t)(b * Tn + qb * 128) * HSn);
        #pragma unroll
        for (int it = 0; it < 8; it++) {
            int idx = it * 256 + t;
            int r = idx >> 4;
            int c = idx & 15;
            *(uint4*)&smh[r * AST + c * 8] = qg[r * 16 + c];
        }
    }
    __syncthreads();

    unsigned qf[8][4];
    {
        const int qrow = w * 16 + (lane & 15);
        const int qch  = (lane >> 4) * 8;
        #pragma unroll
        for (int ks = 0; ks < 8; ks++)
            ldsm4(qf[ks], &smh[qrow * AST + ks * 16 + qch]);
    }
    __syncthreads();

    float o[16][4];
    #pragma unroll
    for (int j = 0; j < 16; j++)
        #pragma unroll
        for (int r = 0; r < 4; r++) o[j][r] = 0.0f;
    float m0 = -1e30f, m1 = -1e30f, l0 = 0.0f, l1 = 0.0f;

    const int rowg0 = qb * 128 + w * 16 + lg;
    const int rowg1 = rowg0 + 8;

    const __half* kbase = g_k + (size_t)b * Tn * HSn;
    const __half* vbase = g_v + (size_t)b * Tn * HSn;

    attn_issue(smh, kbase + (size_t)kt0 * 64 * HSn, vbase + (size_t)kt0 * 64 * HSn, t);

    const int krow = (lane & 7) + (lane >> 4) * 8;     // + jp*16
    const int kch  = ((lane >> 3) & 1) * 8;
    const int vrow = (lane & 7) + ((lane >> 3) & 1) * 8;   // + 16*g
    const int vch  = (lane >> 4) * 8;                      // + j2*16 halfs

    for (int ii = 0; ii < nk; ii++) {
        const int kt = kt0 + ii;
        if (ii + 1 < nk) {
            attn_issue(smh + ((ii + 1) & 1) * STGH,
                       kbase + (size_t)(kt + 1) * 64 * HSn,
                       vbase + (size_t)(kt + 1) * 64 * HSn, t);
            asm volatile("cp.async.wait_group 1;\n" ::);
        } else {
            asm volatile("cp.async.wait_group 0;\n" ::);
        }
        __syncthreads();

        const __half* Ks = smh + (ii & 1) * STGH;
        const __half* Vs = Ks + KHALF;

        // ---- S = Q K^T ----
        float s[8][4];
        #pragma unroll
        for (int j = 0; j < 8; j++)
            #pragma unroll
            for (int r = 0; r < 4; r++) s[j][r] = 0.0f;

        #pragma unroll
        for (int ks = 0; ks < 8; ks++) {
            #pragma unroll
            for (int jp = 0; jp < 4; jp++) {
                unsigned bf[4];
                ldsm4(bf, &Ks[(jp * 16 + krow) * AST + ks * 16 + kch]);
                mma16(s[2 * jp],     qf[ks], bf[0], bf[1]);
                mma16(s[2 * jp + 1], qf[ks], bf[2], bf[3]);
            }
        }

        // ---- causal mask ----
        if (kt * 64 + 63 > qb * 128 + w * 16) {
            #pragma unroll
            for (int j = 0; j < 8; j++) {
                int col = kt * 64 + j * 8 + 2 * lt;
                if (col     > rowg0) s[j][0] = -1e30f;
                if (col + 1 > rowg0) s[j][1] = -1e30f;
                if (col     > rowg1) s[j][2] = -1e30f;
                if (col + 1 > rowg1) s[j][3] = -1e30f;
            }
        }

        // ---- warp-local online softmax ----
        float mx0 = -1e30f, mx1 = -1e30f;
        #pragma unroll
        for (int j = 0; j < 8; j++) {
            mx0 = fmaxf(mx0, fmaxf(s[j][0], s[j][1]));
            mx1 = fmaxf(mx1, fmaxf(s[j][2], s[j][3]));
        }
        mx0 = fmaxf(mx0, __shfl_xor_sync(0xffffffffu, mx0, 1));
        mx0 = fmaxf(mx0, __shfl_xor_sync(0xffffffffu, mx0, 2));
        mx1 = fmaxf(mx1, __shfl_xor_sync(0xffffffffu, mx1, 1));
        mx1 = fmaxf(mx1, __shfl_xor_sync(0xffffffffu, mx1, 2));

        float mn0 = fmaxf(m0, mx0);
        float mn1 = fmaxf(m1, mx1);
        float c0 = __expf(m0 - mn0);
        float c1 = __expf(m1 - mn1);
        m0 = mn0; m1 = mn1;

        float sum0 = 0.0f, sum1 = 0.0f;
        #pragma unroll
        for (int j = 0; j < 8; j++) {
            s[j][0] = __expf(s[j][0] - mn0); sum0 += s[j][0];
            s[j][1] = __expf(s[j][1] - mn0); sum0 += s[j][1];
            s[j][2] = __expf(s[j][2] - mn1); sum1 += s[j][2];
            s[j][3] = __expf(s[j][3] - mn1); sum1 += s[j][3];
        }
        sum0 += __shfl_xor_sync(0xffffffffu, sum0, 1);
        sum0 += __shfl_xor_sync(0xffffffffu, sum0, 2);
        sum1 += __shfl_xor_sync(0xffffffffu, sum1, 1);
        sum1 += __shfl_xor_sync(0xffffffffu, sum1, 2);
        l0 = l0 * c0 + sum0;
        l1 = l1 * c1 + sum1;

        #pragma unroll
        for (int j = 0; j < 16; j++) {
            o[j][0] *= c0; o[j][1] *= c0;
            o[j][2] *= c1; o[j][3] *= c1;
        }

        // ---- O += P V : A-frags pack directly from C-frags, B via ldsm.trans ----
        #pragma unroll
        for (int g = 0; g < 4; g++) {
            unsigned a[4];
            a[0] = packh2(s[2 * g][0],     s[2 * g][1]);
            a[1] = packh2(s[2 * g][2],     s[2 * g][3]);
            a[2] = packh2(s[2 * g + 1][0], s[2 * g + 1][1]);
            a[3] = packh2(s[2 * g + 1][2], s[2 * g + 1][3]);
            #pragma unroll
            for (int jq = 0; jq < 8; jq++) {
                unsigned bf[4];
                ldsm4t(bf, &Vs[(16 * g + vrow) * AST + jq * 16 + vch]);
                mma16(o[2 * jq],     a, bf[0], bf[1]);
                mma16(o[2 * jq + 1], a, bf[2], bf[3]);
            }
        }
        __syncthreads();
    }

    // ---- write partials ----
    {
        float* po = g_po + (size_t)sp * (Bn * Tn * HSn);
        size_t r0 = (size_t)(b * Tn) + rowg0;
        size_t r1 = (size_t)(b * Tn) + rowg1;
        #pragma unroll
        for (int j2 = 0; j2 < 16; j2++) {
            int col = j2 * 8 + 2 * lt;
            *(float2*)&po[r0 * HSn + col] = make_float2(o[j2][0], o[j2][1]);
            *(float2*)&po[r1 * HSn + col] = make_float2(o[j2][2], o[j2][3]);
        }
        if (lt == 0) {
            g_pm[sp * (Bn * Tn) + r0] = m0;
            g_pl[sp * (Bn * Tn) + r0] = l0;
            g_pm[sp * (Bn * Tn) + r1] = m1;
            g_pl[sp * (Bn * Tn) + r1] = l1;
        }
    }
}

// ---------------------------------------------------------------------------
__global__ __launch_bounds__(256) void merge_kernel(float* __restrict__ out)
{
    int i4 = blockIdx.x * 256 + threadIdx.x;
    int row = i4 >> 5;
    float m0 = g_pm[row], m1 = g_pm[Bn * Tn + row];
    float l0 = g_pl[row], l1 = g_pl[Bn * Tn + row];
    float m  = fmaxf(m0, m1);
    float w0 = __expf(m0 - m);
    float w1 = __expf(m1 - m);
    float inv = 1.0f / (l0 * w0 + l1 * w1);
    const float4 a = *(const float4*)&g_po[(size_t)i4 * 4];
    const float4 c = *(const float4*)&g_po[(size_t)(Bn * Tn * HSn) + (size_t)i4 * 4];
    float4 r;
    r.x = (a.x * w0 + c.x * w1) * inv;
    r.y = (a.y * w0 + c.y * w1) * inv;
    r.z = (a.z * w0 + c.z * w1) * inv;
    r.w = (a.w * w0 + c.w * w1) * inv;
    *(float4*)&out[(size_t)i4 * 4] = r;
}

// ---------------------------------------------------------------------------
extern "C" void kernel_launch(void* const* d_in, const int* in_sizes, int n_in,
                              void* d_out, int out_size)
{
    const float* x  = (const float*)d_in[0];
    const float* Wk = (const float*)d_in[1];
    const float* Wq = (const float*)d_in[2];
    const float* Wv = (const float*)d_in[3];
    float* out = (float*)d_out;

    dim3 pg(Bn * Tn / 128, 1, 3);
    proj_kernel<<<pg, 256>>>(x, Wk, Wq, Wv);

    cudaFuncSetAttribute(attn_kernel, cudaFuncAttributeMaxDynamicSharedMemorySize,
                         ATTN_SMEM_BYTES);
    dim3 ag(Bn, 32);
    attn_kernel<<<ag, 256, ATTN_SMEM_BYTES>>>();

    merge_kernel<<<(Bn * Tn * HSn / 4) / 256, 256>>>(out);
}

// round 7
// speedup vs baseline: 9.0524x; 1.1467x over previous
#include <cuda_runtime.h>
#include <cuda_fp16.h>
#include <cstdint>

#define Bn  8
#define Tn  2048
#define Dn  1024
#define HSn 128

// Projected tensors, fp16, natural [B][T][HS] layout.
__device__ __half g_k[Bn * Tn * HSn];
__device__ __half g_q[Bn * Tn * HSn];   // pre-scaled by 1/sqrt(HS)
__device__ __half g_v[Bn * Tn * HSn];
__device__ __half g_wh[3 * HSn * Dn];   // fp16 weights [z][128][1024]
__device__ float  g_po[2 * Bn * Tn * HSn];
__device__ float  g_pm[2 * Bn * Tn];
__device__ float  g_pl[2 * Bn * Tn];

// pack two fp32 -> f16x2 (lo = first arg)
__device__ __forceinline__ unsigned packh2(float lo, float hi) {
    unsigned r;
    asm("cvt.rn.f16x2.f32 %0, %1, %2;" : "=r"(r) : "f"(hi), "f"(lo));
    return r;
}

// mma m16n8k16 fp16 inputs, fp32 accum
__device__ __forceinline__ void mma16(float* c, const unsigned* a,
                                      unsigned b0, unsigned b1) {
    asm volatile(
        "mma.sync.aligned.m16n8k16.row.col.f32.f16.f16.f32 "
        "{%0,%1,%2,%3},{%4,%5,%6,%7},{%8,%9},{%0,%1,%2,%3};"
        : "+f"(c[0]), "+f"(c[1]), "+f"(c[2]), "+f"(c[3])
        : "r"(a[0]), "r"(a[1]), "r"(a[2]), "r"(a[3]), "r"(b0), "r"(b1));
}

__device__ __forceinline__ void ldsm4(unsigned* r, const void* p) {
    unsigned a = (unsigned)__cvta_generic_to_shared(p);
    asm volatile("ldmatrix.sync.aligned.m8n8.x4.shared.b16 {%0,%1,%2,%3}, [%4];"
                 : "=r"(r[0]), "=r"(r[1]), "=r"(r[2]), "=r"(r[3]) : "r"(a));
}

__device__ __forceinline__ void ldsm4t(unsigned* r, const void* p) {
    unsigned a = (unsigned)__cvta_generic_to_shared(p);
    asm volatile("ldmatrix.sync.aligned.m8n8.x4.trans.shared.b16 {%0,%1,%2,%3}, [%4];"
                 : "=r"(r[0]), "=r"(r[1]), "=r"(r[2]), "=r"(r[3]) : "r"(a));
}

__device__ __forceinline__ void cpa16(void* smem_ptr, const void* gptr) {
    unsigned saddr = (unsigned)__cvta_generic_to_shared(smem_ptr);
    asm volatile("cp.async.cg.shared.global [%0], [%1], 16;\n" :: "r"(saddr), "l"(gptr));
}

// ---------------------------------------------------------------------------
// prep: convert Wk/Wq/Wv fp32 -> g_wh fp16 (tiny: 0.75 MB out)
// ---------------------------------------------------------------------------
__global__ __launch_bounds__(256) void prep_w(
    const float* __restrict__ Wk, const float* __restrict__ Wq,
    const float* __restrict__ Wv)
{
    int id = blockIdx.x * 256 + threadIdx.x;     // 0..98303, 4 floats each
    const float* src = (id < 32768) ? Wk : (id < 65536) ? Wq : Wv;
    int off = (id & 32767) * 4;
    float4 v = *(const float4*)(src + off);
    uint2 u;
    u.x = packh2(v.x, v.y);
    u.y = packh2(v.z, v.w);
    *(uint2*)(g_wh + (size_t)id * 4) = u;
}

// ---------------------------------------------------------------------------
// Projection GEMM (fp16 MMA): out[m][n] = sum_d x[m][d] * W[n][d]
// M=16384, N=128, K=1024. BM=128, BN=128, BK=32. 256 threads, 8 warps (4m x 2n).
// x: fp32 LDG + pack + STS (double-buffered, reg-prefetch).
// W: fp16 via cp.async straight into smem (no LDG/STS through registers).
// smem row stride 40 halfs (80B = 5x16B units -> LDSM conflict-free).
// ---------------------------------------------------------------------------
#define PST 40

__device__ __forceinline__ void proj_stsx(__half* Xs, int row, int cb,
    const float4& xa, const float4& xb, const float4& xc, const float4& xd)
{
    uint4 u;
    u.x = packh2(xa.x, xa.y); u.y = packh2(xa.z, xa.w);
    u.z = packh2(xb.x, xb.y); u.w = packh2(xb.z, xb.w);
    *(uint4*)&Xs[row * PST + cb] = u;
    u.x = packh2(xc.x, xc.y); u.y = packh2(xc.z, xc.w);
    u.z = packh2(xd.x, xd.y); u.w = packh2(xd.z, xd.w);
    *(uint4*)&Xs[row * PST + cb + 8] = u;
}

__device__ __forceinline__ void proj_mma(const __half* Xs, const __half* Ws,
                                         float acc[2][8][4],
                                         int wm, int wn, int lane)
{
    const int arow = wm * 32 + (lane & 15);
    const int ach  = (lane >> 4) * 8;
    const int brow = wn * 64 + (lane & 7) + (lane >> 4) * 8;
    const int bch  = ((lane >> 3) & 1) * 8;
    #pragma unroll
    for (int ks = 0; ks < 2; ks++) {
        unsigned af[2][4];
        ldsm4(af[0], &Xs[arow * PST + ks * 16 + ach]);
        ldsm4(af[1], &Xs[(arow + 16) * PST + ks * 16 + ach]);
        #pragma unroll
        for (int jp = 0; jp < 4; jp++) {
            unsigned bf[4];
            ldsm4(bf, &Ws[(brow + jp * 16) * PST + ks * 16 + bch]);
            mma16(acc[0][2 * jp],     af[0], bf[0], bf[1]);
            mma16(acc[1][2 * jp],     af[1], bf[0], bf[1]);
            mma16(acc[0][2 * jp + 1], af[0], bf[2], bf[3]);
            mma16(acc[1][2 * jp + 1], af[1], bf[2], bf[3]);
        }
    }
}

__global__ __launch_bounds__(256, 2) void proj_kernel(const float* __restrict__ x)
{
    __shared__ __half Xs[2][128 * PST];
    __shared__ __half Ws[2][128 * PST];

    const int z = blockIdx.z;
    const __half* wsrc = g_wh + (size_t)z * HSn * Dn;

    const int m0   = blockIdx.x * 128;
    const int t    = threadIdx.x;
    const int lane = t & 31;
    const int w    = t >> 5;
    const int wm   = w & 3;
    const int wn   = w >> 2;
    const int lg   = lane >> 2;
    const int lt   = lane & 3;

    const int lrow = t >> 1;           // 0..127
    const int lcb  = (t & 1) * 16;     // col base 0 or 16 (halfs)

    const float* xrow = x + (size_t)(m0 + lrow) * Dn + lcb;

    // W cp.async mapping: 512 chunks (128 rows x 4 x 16B) -> 2 per thread
    const int wr0 = (t * 2) >> 2;         // row of chunk pair
    const int cu0 = (t * 2) & 3;          // first chunk col-unit

    float acc[2][8][4];
    #pragma unroll
    for (int mf = 0; mf < 2; mf++)
        #pragma unroll
        for (int j = 0; j < 8; j++)
            #pragma unroll
            for (int r = 0; r < 4; r++) acc[mf][j][r] = 0.0f;

    // ---- prologue: stage 0 ----
    float4 xa = *(const float4*)(xrow);
    float4 xb = *(const float4*)(xrow + 4);
    float4 xc = *(const float4*)(xrow + 8);
    float4 xd = *(const float4*)(xrow + 12);
    proj_stsx(Xs[0], lrow, lcb, xa, xb, xc, xd);
    cpa16(&Ws[0][wr0 * PST + cu0 * 8],       wsrc + (size_t)wr0 * Dn + cu0 * 8);
    cpa16(&Ws[0][wr0 * PST + (cu0 + 1) * 8], wsrc + (size_t)wr0 * Dn + (cu0 + 1) * 8);
    asm volatile("cp.async.commit_group;\n" ::);
    // prefetch x for stage 1
    xa = *(const float4*)(xrow + 32); xb = *(const float4*)(xrow + 36);
    xc = *(const float4*)(xrow + 40); xd = *(const float4*)(xrow + 44);

    const int NIT = Dn / 32;   // 32
    for (int i = 0; i < NIT; i++) {
        __syncthreads();          // all warps done with MMA(i-1) (reads buf (i+1)&1)
        if (i + 1 < NIT) {
            proj_stsx(Xs[(i + 1) & 1], lrow, lcb, xa, xb, xc, xd);
            const __half* wp = wsrc + (i + 1) * 32;
            __half* wd = Ws[(i + 1) & 1];
            cpa16(&wd[wr0 * PST + cu0 * 8],       wp + (size_t)wr0 * Dn + cu0 * 8);
            cpa16(&wd[wr0 * PST + (cu0 + 1) * 8], wp + (size_t)wr0 * Dn + (cu0 + 1) * 8);
            asm volatile("cp.async.commit_group;\n" ::);
        }
        if (i + 2 < NIT) {
            const float* xp = xrow + (i + 2) * 32;
            xa = *(const float4*)(xp);      xb = *(const float4*)(xp + 4);
            xc = *(const float4*)(xp + 8);  xd = *(const float4*)(xp + 12);
        }
        if (i + 1 < NIT) asm volatile("cp.async.wait_group 1;\n" ::);
        else             asm volatile("cp.async.wait_group 0;\n" ::);
        __syncthreads();          // W(i) visible to all warps
        proj_mma(Xs[i & 1], Ws[i & 1], acc, wm, wn, lane);
    }

    __half* dst = (z == 0) ? g_k : (z == 1) ? g_q : g_v;
    const float qscale = (z == 1) ? 0.08838834764831845f : 1.0f;
    #pragma unroll
    for (int mf = 0; mf < 2; mf++)
        #pragma unroll
        for (int j = 0; j < 8; j++) {
            int row = m0 + wm * 32 + mf * 16 + lg;
            int col = wn * 64 + j * 8 + 2 * lt;
            *(unsigned*)&dst[(size_t)row * HSn + col] =
                packh2(acc[mf][j][0] * qscale, acc[mf][j][1] * qscale);
            *(unsigned*)&dst[(size_t)(row + 8) * HSn + col] =
                packh2(acc[mf][j][2] * qscale, acc[mf][j][3] * qscale);
        }
}

// ---------------------------------------------------------------------------
// Flash attention (round-5, passing): fp16 MMA, BM=128, BN=64, split-K x2,
// cp.async double buffer, LDSM fragments, V via ldmatrix.trans.
// ---------------------------------------------------------------------------
#define AST 136
#define KHALF (64 * AST)
#define STGH  (2 * KHALF)
#define ATTN_SMEM_BYTES (2 * STGH * 2)

__device__ __forceinline__ void attn_issue(__half* stage, const __half* kg,
                                           const __half* vg, int t) {
    __half* Ks = stage;
    __half* Vs = stage + KHALF;
    #pragma unroll
    for (int ch = 0; ch < 4; ch++) {
        int idx = ch * 256 + t;
        int r = idx >> 4;
        int c = (idx & 15) * 8;
        cpa16(&Ks[r * AST + c], kg + (size_t)r * HSn + c);
        cpa16(&Vs[r * AST + c], vg + (size_t)r * HSn + c);
    }
    asm volatile("cp.async.commit_group;\n" ::);
}

__global__ __launch_bounds__(256) void attn_kernel()
{
    extern __shared__ __half smh[];

    const int b    = blockIdx.x;
    const int item = blockIdx.y;
    const int qb   = 15 - (item >> 1);
    const int sp   = item & 1;
    const int kt0  = sp ? (qb + 1) : 0;
    const int nk   = qb + 1;

    const int t    = threadIdx.x;
    const int lane = t & 31;
    const int w    = t >> 5;
    const int lg   = lane >> 2;
    const int lt   = lane & 3;

    {
        const uint4* qg = (const uint4*)(g_q + (size_t)(b * Tn + qb * 128) * HSn);
        #pragma unroll
        for (int it = 0; it < 8; it++) {
            int idx = it * 256 + t;
            int r = idx >> 4;
            int c = idx & 15;
            *(uint4*)&smh[r * AST + c * 8] = qg[r * 16 + c];
        }
    }
    __syncthreads();

    unsigned qf[8][4];
    {
        const int qrow = w * 16 + (lane & 15);
        const int qch  = (lane >> 4) * 8;
        #pragma unroll
        for (int ks = 0; ks < 8; ks++)
            ldsm4(qf[ks], &smh[qrow * AST + ks * 16 + qch]);
    }
    __syncthreads();

    float o[16][4];
    #pragma unroll
    for (int j = 0; j < 16; j++)
        #pragma unroll
        for (int r = 0; r < 4; r++) o[j][r] = 0.0f;
    float m0 = -1e30f, m1 = -1e30f, l0 = 0.0f, l1 = 0.0f;

    const int rowg0 = qb * 128 + w * 16 + lg;
    const int rowg1 = rowg0 + 8;

    const __half* kbase = g_k + (size_t)b * Tn * HSn;
    const __half* vbase = g_v + (size_t)b * Tn * HSn;

    attn_issue(smh, kbase + (size_t)kt0 * 64 * HSn, vbase + (size_t)kt0 * 64 * HSn, t);

    const int krow = (lane & 7) + (lane >> 4) * 8;
    const int kch  = ((lane >> 3) & 1) * 8;
    const int vrow = (lane & 7) + ((lane >> 3) & 1) * 8;
    const int vch  = (lane >> 4) * 8;

    for (int ii = 0; ii < nk; ii++) {
        const int kt = kt0 + ii;
        if (ii + 1 < nk) {
            attn_issue(smh + ((ii + 1) & 1) * STGH,
                       kbase + (size_t)(kt + 1) * 64 * HSn,
                       vbase + (size_t)(kt + 1) * 64 * HSn, t);
            asm volatile("cp.async.wait_group 1;\n" ::);
        } else {
            asm volatile("cp.async.wait_group 0;\n" ::);
        }
        __syncthreads();

        const __half* Ks = smh + (ii & 1) * STGH;
        const __half* Vs = Ks + KHALF;

        float s[8][4];
        #pragma unroll
        for (int j = 0; j < 8; j++)
            #pragma unroll
            for (int r = 0; r < 4; r++) s[j][r] = 0.0f;

        #pragma unroll
        for (int ks = 0; ks < 8; ks++) {
            #pragma unroll
            for (int jp = 0; jp < 4; jp++) {
                unsigned bf[4];
                ldsm4(bf, &Ks[(jp * 16 + krow) * AST + ks * 16 + kch]);
                mma16(s[2 * jp],     qf[ks], bf[0], bf[1]);
                mma16(s[2 * jp + 1], qf[ks], bf[2], bf[3]);
            }
        }

        if (kt * 64 + 63 > qb * 128 + w * 16) {
            #pragma unroll
            for (int j = 0; j < 8; j++) {
                int col = kt * 64 + j * 8 + 2 * lt;
                if (col     > rowg0) s[j][0] = -1e30f;
                if (col + 1 > rowg0) s[j][1] = -1e30f;
                if (col     > rowg1) s[j][2] = -1e30f;
                if (col + 1 > rowg1) s[j][3] = -1e30f;
            }
        }

        float mx0 = -1e30f, mx1 = -1e30f;
        #pragma unroll
        for (int j = 0; j < 8; j++) {
            mx0 = fmaxf(mx0, fmaxf(s[j][0], s[j][1]));
            mx1 = fmaxf(mx1, fmaxf(s[j][2], s[j][3]));
        }
        mx0 = fmaxf(mx0, __shfl_xor_sync(0xffffffffu, mx0, 1));
        mx0 = fmaxf(mx0, __shfl_xor_sync(0xffffffffu, mx0, 2));
        mx1 = fmaxf(mx1, __shfl_xor_sync(0xffffffffu, mx1, 1));
        mx1 = fmaxf(mx1, __shfl_xor_sync(0xffffffffu, mx1, 2));

        float mn0 = fmaxf(m0, mx0);
        float mn1 = fmaxf(m1, mx1);
        float c0 = __expf(m0 - mn0);
        float c1 = __expf(m1 - mn1);
        m0 = mn0; m1 = mn1;

        float sum0 = 0.0f, sum1 = 0.0f;
        #pragma unroll
        for (int j = 0; j < 8; j++) {
            s[j][0] = __expf(s[j][0] - mn0); sum0 += s[j][0];
            s[j][1] = __expf(s[j][1] - mn0); sum0 += s[j][1];
            s[j][2] = __expf(s[j][2] - mn1); sum1 += s[j][2];
            s[j][3] = __expf(s[j][3] - mn1); sum1 += s[j][3];
        }
        sum0 += __shfl_xor_sync(0xffffffffu, sum0, 1);
        sum0 += __shfl_xor_sync(0xffffffffu, sum0, 2);
        sum1 += __shfl_xor_sync(0xffffffffu, sum1, 1);
        sum1 += __shfl_xor_sync(0xffffffffu, sum1, 2);
        l0 = l0 * c0 + sum0;
        l1 = l1 * c1 + sum1;

        #pragma unroll
        for (int j = 0; j < 16; j++) {
            o[j][0] *= c0; o[j][1] *= c0;
            o[j][2] *= c1; o[j][3] *= c1;
        }

        #pragma unroll
        for (int g = 0; g < 4; g++) {
            unsigned a[4];
            a[0] = packh2(s[2 * g][0],     s[2 * g][1]);
            a[1] = packh2(s[2 * g][2],     s[2 * g][3]);
            a[2] = packh2(s[2 * g + 1][0], s[2 * g + 1][1]);
            a[3] = packh2(s[2 * g + 1][2], s[2 * g + 1][3]);
            #pragma unroll
            for (int jq = 0; jq < 8; jq++) {
                unsigned bf[4];
                ldsm4t(bf, &Vs[(16 * g + vrow) * AST + jq * 16 + vch]);
                mma16(o[2 * jq],     a, bf[0], bf[1]);
                mma16(o[2 * jq + 1], a, bf[2], bf[3]);
            }
        }
        __syncthreads();
    }

    {
        float* po = g_po + (size_t)sp * (Bn * Tn * HSn);
        size_t r0 = (size_t)(b * Tn) + rowg0;
        size_t r1 = (size_t)(b * Tn) + rowg1;
        #pragma unroll
        for (int j2 = 0; j2 < 16; j2++) {
            int col = j2 * 8 + 2 * lt;
            *(float2*)&po[r0 * HSn + col] = make_float2(o[j2][0], o[j2][1]);
            *(float2*)&po[r1 * HSn + col] = make_float2(o[j2][2], o[j2][3]);
        }
        if (lt == 0) {
            g_pm[sp * (Bn * Tn) + r0] = m0;
            g_pl[sp * (Bn * Tn) + r0] = l0;
            g_pm[sp * (Bn * Tn) + r1] = m1;
            g_pl[sp * (Bn * Tn) + r1] = l1;
        }
    }
}

// ---------------------------------------------------------------------------
__global__ __launch_bounds__(256) void merge_kernel(float* __restrict__ out)
{
    int i4 = blockIdx.x * 256 + threadIdx.x;
    int row = i4 >> 5;
    float m0 = g_pm[row], m1 = g_pm[Bn * Tn + row];
    float l0 = g_pl[row], l1 = g_pl[Bn * Tn + row];
    float m  = fmaxf(m0, m1);
    float w0 = __expf(m0 - m);
    float w1 = __expf(m1 - m);
    float inv = 1.0f / (l0 * w0 + l1 * w1);
    const float4 a = *(const float4*)&g_po[(size_t)i4 * 4];
    const float4 c = *(const float4*)&g_po[(size_t)(Bn * Tn * HSn) + (size_t)i4 * 4];
    float4 r;
    r.x = (a.x * w0 + c.x * w1) * inv;
    r.y = (a.y * w0 + c.y * w1) * inv;
    r.z = (a.z * w0 + c.z * w1) * inv;
    r.w = (a.w * w0 + c.w * w1) * inv;
    *(float4*)&out[(size_t)i4 * 4] = r;
}

// ---------------------------------------------------------------------------
extern "C" void kernel_launch(void* const* d_in, const int* in_sizes, int n_in,
                              void* d_out, int out_size)
{
    const float* x  = (const float*)d_in[0];
    const float* Wk = (const float*)d_in[1];
    const float* Wq = (const float*)d_in[2];
    const float* Wv = (const float*)d_in[3];
    float* out = (float*)d_out;

    prep_w<<<384, 256>>>(Wk, Wq, Wv);

    dim3 pg(Bn * Tn / 128, 1, 3);
    proj_kernel<<<pg, 256>>>(x);

    cudaFuncSetAttribute(attn_kernel, cudaFuncAttributeMaxDynamicSharedMemorySize,
                         ATTN_SMEM_BYTES);
    dim3 ag(Bn, 32);
    attn_kernel<<<ag, 256, ATTN_SMEM_BYTES>>>();

    merge_kernel<<<(Bn * Tn * HSn / 4) / 256, 256>>>(out);
}

// round 8
// speedup vs baseline: 9.4368x; 1.0425x over previous
#include <cuda_runtime.h>
#include <cuda_fp16.h>
#include <cstdint>

#define Bn  8
#define Tn  2048
#define Dn  1024
#define HSn 128

// Projected tensors, fp16, natural [B][T][HS] layout.
__device__ __half g_k[Bn * Tn * HSn];
__device__ __half g_q[Bn * Tn * HSn];   // pre-scaled by 1/sqrt(HS)
__device__ __half g_v[Bn * Tn * HSn];
__device__ __half g_wh[3 * HSn * Dn];   // fp16 weights [z][128][1024]
__device__ __half g_po[2 * Bn * Tn * HSn];   // fp16 split-K partials
__device__ float  g_pm[2 * Bn * Tn];
__device__ float  g_pl[2 * Bn * Tn];

__device__ __forceinline__ unsigned packh2(float lo, float hi) {
    unsigned r;
    asm("cvt.rn.f16x2.f32 %0, %1, %2;" : "=r"(r) : "f"(hi), "f"(lo));
    return r;
}

__device__ __forceinline__ void mma16(float* c, const unsigned* a,
                                      unsigned b0, unsigned b1) {
    asm volatile(
        "mma.sync.aligned.m16n8k16.row.col.f32.f16.f16.f32 "
        "{%0,%1,%2,%3},{%4,%5,%6,%7},{%8,%9},{%0,%1,%2,%3};"
        : "+f"(c[0]), "+f"(c[1]), "+f"(c[2]), "+f"(c[3])
        : "r"(a[0]), "r"(a[1]), "r"(a[2]), "r"(a[3]), "r"(b0), "r"(b1));
}

__device__ __forceinline__ void ldsm4(unsigned* r, const void* p) {
    unsigned a = (unsigned)__cvta_generic_to_shared(p);
    asm volatile("ldmatrix.sync.aligned.m8n8.x4.shared.b16 {%0,%1,%2,%3}, [%4];"
                 : "=r"(r[0]), "=r"(r[1]), "=r"(r[2]), "=r"(r[3]) : "r"(a));
}

__device__ __forceinline__ void ldsm4t(unsigned* r, const void* p) {
    unsigned a = (unsigned)__cvta_generic_to_shared(p);
    asm volatile("ldmatrix.sync.aligned.m8n8.x4.trans.shared.b16 {%0,%1,%2,%3}, [%4];"
                 : "=r"(r[0]), "=r"(r[1]), "=r"(r[2]), "=r"(r[3]) : "r"(a));
}

__device__ __forceinline__ void cpa16(void* smem_ptr, const void* gptr) {
    unsigned saddr = (unsigned)__cvta_generic_to_shared(smem_ptr);
    asm volatile("cp.async.cg.shared.global [%0], [%1], 16;\n" :: "r"(saddr), "l"(gptr));
}

// ---------------------------------------------------------------------------
// prep: convert Wk/Wq/Wv fp32 -> g_wh fp16
// ---------------------------------------------------------------------------
__global__ __launch_bounds__(256) void prep_w(
    const float* __restrict__ Wk, const float* __restrict__ Wq,
    const float* __restrict__ Wv)
{
    int id = blockIdx.x * 256 + threadIdx.x;
    const float* src = (id < 32768) ? Wk : (id < 65536) ? Wq : Wv;
    int off = (id & 32767) * 4;
    float4 v = *(const float4*)(src + off);
    uint2 u;
    u.x = packh2(v.x, v.y);
    u.y = packh2(v.z, v.w);
    *(uint2*)(g_wh + (size_t)id * 4) = u;
}

// ---------------------------------------------------------------------------
// Projection GEMM (fp16 MMA, 3-stage pipeline, one barrier per stage).
// M=16384, N=128, K=1024. BM=128, BN=128, BK=32. 256 threads, 8 warps (4m x 2n).
// ---------------------------------------------------------------------------
#define PST 40
#define PXH (128 * PST)          // halfs per X stage (5120)
#define PSTGH (2 * PXH)          // halfs per full stage (X + W)
#define PROJ_SMEM_BYTES (3 * PSTGH * 2)   // 61440 B

__device__ __forceinline__ void proj_stsx(__half* Xs, int row, int cb,
    const float4& xa, const float4& xb, const float4& xc, const float4& xd)
{
    uint4 u;
    u.x = packh2(xa.x, xa.y); u.y = packh2(xa.z, xa.w);
    u.z = packh2(xb.x, xb.y); u.w = packh2(xb.z, xb.w);
    *(uint4*)&Xs[row * PST + cb] = u;
    u.x = packh2(xc.x, xc.y); u.y = packh2(xc.z, xc.w);
    u.z = packh2(xd.x, xd.y); u.w = packh2(xd.z, xd.w);
    *(uint4*)&Xs[row * PST + cb + 8] = u;
}

__device__ __forceinline__ void proj_mma(const __half* Xs, const __half* Ws,
                                         float acc[2][8][4],
                                         int wm, int wn, int lane)
{
    const int arow = wm * 32 + (lane & 15);
    const int ach  = (lane >> 4) * 8;
    const int brow = wn * 64 + (lane & 7) + (lane >> 4) * 8;
    const int bch  = ((lane >> 3) & 1) * 8;
    #pragma unroll
    for (int ks = 0; ks < 2; ks++) {
        unsigned af[2][4];
        ldsm4(af[0], &Xs[arow * PST + ks * 16 + ach]);
        ldsm4(af[1], &Xs[(arow + 16) * PST + ks * 16 + ach]);
        #pragma unroll
        for (int jp = 0; jp < 4; jp++) {
            unsigned bf[4];
            ldsm4(bf, &Ws[(brow + jp * 16) * PST + ks * 16 + bch]);
            mma16(acc[0][2 * jp],     af[0], bf[0], bf[1]);
            mma16(acc[1][2 * jp],     af[1], bf[0], bf[1]);
            mma16(acc[0][2 * jp + 1], af[0], bf[2], bf[3]);
            mma16(acc[1][2 * jp + 1], af[1], bf[2], bf[3]);
        }
    }
}

__global__ __launch_bounds__(256, 2) void proj_kernel(const float* __restrict__ x)
{
    extern __shared__ __half psm[];

    const int z = blockIdx.z;
    const __half* wsrc = g_wh + (size_t)z * HSn * Dn;

    const int m0   = blockIdx.x * 128;
    const int t    = threadIdx.x;
    const int lane = t & 31;
    const int w    = t >> 5;
    const int wm   = w & 3;
    const int wn   = w >> 2;
    const int lg   = lane >> 2;
    const int lt   = lane & 3;

    const int lrow = t >> 1;
    const int lcb  = (t & 1) * 16;

    const float* xrow = x + (size_t)(m0 + lrow) * Dn + lcb;

    const int wr0 = (t * 2) >> 2;
    const int cu0 = (t * 2) & 3;

    float acc[2][8][4];
    #pragma unroll
    for (int mf = 0; mf < 2; mf++)
        #pragma unroll
        for (int j = 0; j < 8; j++)
            #pragma unroll
            for (int r = 0; r < 4; r++) acc[mf][j][r] = 0.0f;

    float4 xa, xb, xc, xd;
    // ---- prologue: stages 0, 1 staged; stage 2's x in regs ----
    #pragma unroll
    for (int s = 0; s < 2; s++) {
        const float* xp = xrow + s * 32;
        xa = *(const float4*)(xp);      xb = *(const float4*)(xp + 4);
        xc = *(const float4*)(xp + 8);  xd = *(const float4*)(xp + 12);
        proj_stsx(psm + s * PSTGH, lrow, lcb, xa, xb, xc, xd);
        __half* wd = psm + s * PSTGH + PXH;
        const __half* wp = wsrc + s * 32;
        cpa16(&wd[wr0 * PST + cu0 * 8],       wp + (size_t)wr0 * Dn + cu0 * 8);
        cpa16(&wd[wr0 * PST + (cu0 + 1) * 8], wp + (size_t)wr0 * Dn + (cu0 + 1) * 8);
        asm volatile("cp.async.commit_group;\n" ::);
    }
    {
        const float* xp = xrow + 64;
        xa = *(const float4*)(xp);      xb = *(const float4*)(xp + 4);
        xc = *(const float4*)(xp + 8);  xd = *(const float4*)(xp + 12);
    }

    const int NIT = Dn / 32;   // 32
    for (int i = 0; i < NIT; i++) {
        if (i == NIT - 1) asm volatile("cp.async.wait_group 0;\n" ::);
        else              asm volatile("cp.async.wait_group 1;\n" ::);
        __syncthreads();     // stage i visible; all warps done with MMA(i-1)
        if (i + 2 < NIT) {
            int s = (i + 2) % 3;
            proj_stsx(psm + s * PSTGH, lrow, lcb, xa, xb, xc, xd);
            __half* wd = psm + s * PSTGH + PXH;
            const __half* wp = wsrc + (i + 2) * 32;
            cpa16(&wd[wr0 * PST + cu0 * 8],       wp + (size_t)wr0 * Dn + cu0 * 8);
            cpa16(&wd[wr0 * PST + (cu0 + 1) * 8], wp + (size_t)wr0 * Dn + (cu0 + 1) * 8);
            asm volatile("cp.async.commit_group;\n" ::);
        }
        if (i + 3 < NIT) {
            const float* xp = xrow + (i + 3) * 32;
            xa = *(const float4*)(xp);      xb = *(const float4*)(xp + 4);
            xc = *(const float4*)(xp + 8);  xd = *(const float4*)(xp + 12);
        }
        int sc = i % 3;
        proj_mma(psm + sc * PSTGH, psm + sc * PSTGH + PXH, acc, wm, wn, lane);
    }

    __half* dst = (z == 0) ? g_k : (z == 1) ? g_q : g_v;
    const float qscale = (z == 1) ? 0.08838834764831845f : 1.0f;
    #pragma unroll
    for (int mf = 0; mf < 2; mf++)
        #pragma unroll
        for (int j = 0; j < 8; j++) {
            int row = m0 + wm * 32 + mf * 16 + lg;
            int col = wn * 64 + j * 8 + 2 * lt;
            *(unsigned*)&dst[(size_t)row * HSn + col] =
                packh2(acc[mf][j][0] * qscale, acc[mf][j][1] * qscale);
            *(unsigned*)&dst[(size_t)(row + 8) * HSn + col] =
                packh2(acc[mf][j][2] * qscale, acc[mf][j][3] * qscale);
        }
}

// ---------------------------------------------------------------------------
// Flash attention: fp16 MMA, BM=128, BN=64, split-K x2,
// 3-stage cp.async pipeline with ONE barrier per iteration.
// ---------------------------------------------------------------------------
#define AST 136
#define KHALF (64 * AST)
#define STGH  (2 * KHALF)                 // halfs per stage (K + V)
#define ATTN_SMEM_BYTES (3 * STGH * 2)    // 104448 B

__device__ __forceinline__ void attn_issue(__half* stage, const __half* kg,
                                           const __half* vg, int t) {
    __half* Ks = stage;
    __half* Vs = stage + KHALF;
    #pragma unroll
    for (int ch = 0; ch < 4; ch++) {
        int idx = ch * 256 + t;
        int r = idx >> 4;
        int c = (idx & 15) * 8;
        cpa16(&Ks[r * AST + c], kg + (size_t)r * HSn + c);
        cpa16(&Vs[r * AST + c], vg + (size_t)r * HSn + c);
    }
    asm volatile("cp.async.commit_group;\n" ::);
}

__global__ __launch_bounds__(256) void attn_kernel()
{
    extern __shared__ __half smh[];

    const int b    = blockIdx.x;
    const int item = blockIdx.y;
    const int qb   = 15 - (item >> 1);
    const int sp   = item & 1;
    const int kt0  = sp ? (qb + 1) : 0;
    const int nk   = qb + 1;

    const int t    = threadIdx.x;
    const int lane = t & 31;
    const int w    = t >> 5;
    const int lg   = lane >> 2;
    const int lt   = lane & 3;

    // ---- stage Q tile (raw copy) into stage-0 region; read A-fragments ----
    {
        const uint4* qg = (const uint4*)(g_q + (size_t)(b * Tn + qb * 128) * HSn);
        #pragma unroll
        for (int it = 0; it < 8; it++) {
            int idx = it * 256 + t;
            int r = idx >> 4;
            int c = idx & 15;
            *(uint4*)&smh[r * AST + c * 8] = qg[r * 16 + c];
        }
    }
    __syncthreads();

    unsigned qf[8][4];
    {
        const int qrow = w * 16 + (lane & 15);
        const int qch  = (lane >> 4) * 8;
        #pragma unroll
        for (int ks = 0; ks < 8; ks++)
            ldsm4(qf[ks], &smh[qrow * AST + ks * 16 + qch]);
    }
    __syncthreads();   // Q reads done; stage buffers may be overwritten

    float o[16][4];
    #pragma unroll
    for (int j = 0; j < 16; j++)
        #pragma unroll
        for (int r = 0; r < 4; r++) o[j][r] = 0.0f;
    float m0 = -1e30f, m1 = -1e30f, l0 = 0.0f, l1 = 0.0f;

    const int rowg0 = qb * 128 + w * 16 + lg;
    const int rowg1 = rowg0 + 8;

    const __half* kbase = g_k + (size_t)b * Tn * HSn;
    const __half* vbase = g_v + (size_t)b * Tn * HSn;

    // prologue: stages 0 and 1
    attn_issue(smh, kbase + (size_t)kt0 * 64 * HSn, vbase + (size_t)kt0 * 64 * HSn, t);
    if (nk > 1)
        attn_issue(smh + STGH, kbase + (size_t)(kt0 + 1) * 64 * HSn,
                   vbase + (size_t)(kt0 + 1) * 64 * HSn, t);

    const int krow = (lane & 7) + (lane >> 4) * 8;
    const int kch  = ((lane >> 3) & 1) * 8;
    const int vrow = (lane & 7) + ((lane >> 3) & 1) * 8;
    const int vch  = (lane >> 4) * 8;

    for (int ii = 0; ii < nk; ii++) {
        const int kt = kt0 + ii;
        if (ii == nk - 1) asm volatile("cp.async.wait_group 0;\n" ::);
        else              asm volatile("cp.async.wait_group 1;\n" ::);
        __syncthreads();   // stage ii visible; all warps done with iter ii-1
        if (ii + 2 < nk)
            attn_issue(smh + ((ii + 2) % 3) * STGH,
                       kbase + (size_t)(kt + 2) * 64 * HSn,
                       vbase + (size_t)(kt + 2) * 64 * HSn, t);

        const __half* Ks = smh + (ii % 3) * STGH;
        const __half* Vs = Ks + KHALF;

        // ---- S = Q K^T ----
        float s[8][4];
        #pragma unroll
        for (int j = 0; j < 8; j++)
            #pragma unroll
            for (int r = 0; r < 4; r++) s[j][r] = 0.0f;

        #pragma unroll
        for (int ks = 0; ks < 8; ks++) {
            #pragma unroll
            for (int jp = 0; jp < 4; jp++) {
                unsigned bf[4];
                ldsm4(bf, &Ks[(jp * 16 + krow) * AST + ks * 16 + kch]);
                mma16(s[2 * jp],     qf[ks], bf[0], bf[1]);
                mma16(s[2 * jp + 1], qf[ks], bf[2], bf[3]);
            }
        }

        // ---- causal mask ----
        if (kt * 64 + 63 > qb * 128 + w * 16) {
            #pragma unroll
            for (int j = 0; j < 8; j++) {
                int col = kt * 64 + j * 8 + 2 * lt;
                if (col     > rowg0) s[j][0] = -1e30f;
                if (col + 1 > rowg0) s[j][1] = -1e30f;
                if (col     > rowg1) s[j][2] = -1e30f;
                if (col + 1 > rowg1) s[j][3] = -1e30f;
            }
        }

        // ---- warp-local online softmax ----
        float mx0 = -1e30f, mx1 = -1e30f;
        #pragma unroll
        for (int j = 0; j < 8; j++) {
            mx0 = fmaxf(mx0, fmaxf(s[j][0], s[j][1]));
            mx1 = fmaxf(mx1, fmaxf(s[j][2], s[j][3]));
        }
        mx0 = fmaxf(mx0, __shfl_xor_sync(0xffffffffu, mx0, 1));
        mx0 = fmaxf(mx0, __shfl_xor_sync(0xffffffffu, mx0, 2));
        mx1 = fmaxf(mx1, __shfl_xor_sync(0xffffffffu, mx1, 1));
        mx1 = fmaxf(mx1, __shfl_xor_sync(0xffffffffu, mx1, 2));

        float mn0 = fmaxf(m0, mx0);
        float mn1 = fmaxf(m1, mx1);
        float c0 = __expf(m0 - mn0);
        float c1 = __expf(m1 - mn1);
        m0 = mn0; m1 = mn1;

        float sum0 = 0.0f, sum1 = 0.0f;
        #pragma unroll
        for (int j = 0; j < 8; j++) {
            s[j][0] = __expf(s[j][0] - mn0); sum0 += s[j][0];
            s[j][1] = __expf(s[j][1] - mn0); sum0 += s[j][1];
            s[j][2] = __expf(s[j][2] - mn1); sum1 += s[j][2];
            s[j][3] = __expf(s[j][3] - mn1); sum1 += s[j][3];
        }
        sum0 += __shfl_xor_sync(0xffffffffu, sum0, 1);
        sum0 += __shfl_xor_sync(0xffffffffu, sum0, 2);
        sum1 += __shfl_xor_sync(0xffffffffu, sum1, 1);
        sum1 += __shfl_xor_sync(0xffffffffu, sum1, 2);
        l0 = l0 * c0 + sum0;
        l1 = l1 * c1 + sum1;

        #pragma unroll
        for (int j = 0; j < 16; j++) {
            o[j][0] *= c0; o[j][1] *= c0;
            o[j][2] *= c1; o[j][3] *= c1;
        }

        // ---- O += P V ----
        #pragma unroll
        for (int g = 0; g < 4; g++) {
            unsigned a[4];
            a[0] = packh2(s[2 * g][0],     s[2 * g][1]);
            a[1] = packh2(s[2 * g][2],     s[2 * g][3]);
            a[2] = packh2(s[2 * g + 1][0], s[2 * g + 1][1]);
            a[3] = packh2(s[2 * g + 1][2], s[2 * g + 1][3]);
            #pragma unroll
            for (int jq = 0; jq < 8; jq++) {
                unsigned bf[4];
                ldsm4t(bf, &Vs[(16 * g + vrow) * AST + jq * 16 + vch]);
                mma16(o[2 * jq],     a, bf[0], bf[1]);
                mma16(o[2 * jq + 1], a, bf[2], bf[3]);
            }
        }
    }

    // ---- write fp16 partials ----
    {
        __half* po = g_po + (size_t)sp * (Bn * Tn * HSn);
        size_t r0 = (size_t)(b * Tn) + rowg0;
        size_t r1 = (size_t)(b * Tn) + rowg1;
        #pragma unroll
        for (int j2 = 0; j2 < 16; j2++) {
            int col = j2 * 8 + 2 * lt;
            *(unsigned*)&po[r0 * HSn + col] = packh2(o[j2][0], o[j2][1]);
            *(unsigned*)&po[r1 * HSn + col] = packh2(o[j2][2], o[j2][3]);
        }
        if (lt == 0) {
            g_pm[sp * (Bn * Tn) + r0] = m0;
            g_pl[sp * (Bn * Tn) + r0] = l0;
            g_pm[sp * (Bn * Tn) + r1] = m1;
            g_pl[sp * (Bn * Tn) + r1] = l1;
        }
    }
}

// ---------------------------------------------------------------------------
__global__ __launch_bounds__(256) void merge_kernel(float* __restrict__ out)
{
    int i4 = blockIdx.x * 256 + threadIdx.x;      // 4 output floats each
    int row = i4 >> 5;
    float m0 = g_pm[row], m1 = g_pm[Bn * Tn + row];
    float l0 = g_pl[row], l1 = g_pl[Bn * Tn + row];
    float m  = fmaxf(m0, m1);
    float w0 = __expf(m0 - m);
    float w1 = __expf(m1 - m);
    float inv = 1.0f / (l0 * w0 + l1 * w1);
    uint2 ua = *(const uint2*)(g_po + (size_t)i4 * 4);
    uint2 uc = *(const uint2*)(g_po + (size_t)(Bn * Tn * HSn) + (size_t)i4 * 4);
    float2 a0 = __half22float2(*(const __half2*)&ua.x);
    float2 a1 = __half22float2(*(const __half2*)&ua.y);
    float2 c0 = __half22float2(*(const __half2*)&uc.x);
    float2 c1 = __half22float2(*(const __half2*)&uc.y);
    float4 r;
    r.x = (a0.x * w0 + c0.x * w1) * inv;
    r.y = (a0.y * w0 + c0.y * w1) * inv;
    r.z = (a1.x * w0 + c1.x * w1) * inv;
    r.w = (a1.y * w0 + c1.y * w1) * inv;
    *(float4*)&out[(size_t)i4 * 4] = r;
}

// ---------------------------------------------------------------------------
extern "C" void kernel_launch(void* const* d_in, const int* in_sizes, int n_in,
                              void* d_out, int out_size)
{
    const float* x  = (const float*)d_in[0];
    const float* Wk = (const float*)d_in[1];
    const float* Wq = (const float*)d_in[2];
    const float* Wv = (const float*)d_in[3];
    float* out = (float*)d_out;

    prep_w<<<384, 256>>>(Wk, Wq, Wv);

    cudaFuncSetAttribute(proj_kernel, cudaFuncAttributeMaxDynamicSharedMemorySize,
                         PROJ_SMEM_BYTES);
    dim3 pg(Bn * Tn / 128, 1, 3);
    proj_kernel<<<pg, 256, PROJ_SMEM_BYTES>>>(x);

    cudaFuncSetAttribute(attn_kernel, cudaFuncAttributeMaxDynamicSharedMemorySize,
                         ATTN_SMEM_BYTES);
    dim3 ag(Bn, 32);
    attn_kernel<<<ag, 256, ATTN_SMEM_BYTES>>>();

    merge_kernel<<<(Bn * Tn * HSn / 4) / 256, 256>>>(out);
}